// round 2
// baseline (speedup 1.0000x reference)
#include <cuda_runtime.h>
#include <cstdint>

// Problem constants
#define BB 4
#define SS 2048
#define DD 1024
#define HH 16
#define DHH 64
#define BSROWS (BB * SS)          // 8192

// Scratch (device globals: allocation-free)
__device__ float g_q[(size_t)BSROWS * DD];
__device__ float g_k[(size_t)BSROWS * DD];
__device__ float g_v[(size_t)BSROWS * DD];
__device__ float g_att[(size_t)BSROWS * DD];

#define LOG2E 1.4426950408889634f
#define INV_SCALE 0.125f          // 1/sqrt(64)

// ---------------------------------------------------------------------------
// m16n8k8 TF32 mma
// ---------------------------------------------------------------------------
__device__ __forceinline__ void mma_tf32(float* c, const float* a, const float* b) {
    const unsigned* A = reinterpret_cast<const unsigned*>(a);
    const unsigned* B = reinterpret_cast<const unsigned*>(b);
    asm volatile(
        "mma.sync.aligned.m16n8k8.row.col.f32.tf32.tf32.f32 "
        "{%0,%1,%2,%3}, {%4,%5,%6,%7}, {%8,%9}, {%0,%1,%2,%3};\n"
        : "+f"(c[0]), "+f"(c[1]), "+f"(c[2]), "+f"(c[3])
        : "r"(A[0]), "r"(A[1]), "r"(A[2]), "r"(A[3]),
          "r"(B[0]), "r"(B[1]));
}

// Split fp32 -> (hi, lo) tf32 pair. hi+lo reproduces x to ~2^-21 rel.
__device__ __forceinline__ void tf32split(float x, float& hi, float& lo) {
    unsigned h;
    asm("cvt.rna.tf32.f32 %0, %1;" : "=r"(h) : "f"(x));
    hi = __uint_as_float(h);
    float r = x - hi;
    unsigned l;
    asm("cvt.rna.tf32.f32 %0, %1;" : "=r"(l) : "f"(r));
    lo = __uint_as_float(l);
}

__device__ __forceinline__ void split4(float4 v, float4& h, float4& l) {
    tf32split(v.x, h.x, l.x);
    tf32split(v.y, h.y, l.y);
    tf32split(v.z, h.z, l.z);
    tf32split(v.w, h.w, l.w);
}

// ---------------------------------------------------------------------------
// GEMM (3xTF32): C[M,N] = A[M,1024] * W[1024,N] + bias, M=8192, N=K=1024
// CTA tile 128x128, kstep 16, 256 threads (8 warps: 4 along M x 2 along N)
// mode: 0/1/2 -> C = g_q/g_k/g_v (A = Aext);  3 -> A = g_att, C = Cext
// ---------------------------------------------------------------------------
#define GEMM_SMEM ((2*128*20*2 + 2*16*136*2) * 4)   // 75776 bytes

__global__ __launch_bounds__(256)
void gemm_bias_3xtf32(const float* __restrict__ Aext,
                      const float* __restrict__ W,
                      const float* __restrict__ bias,
                      float* __restrict__ Cext, int mode)
{
    const int N = DD, K = DD;
    const float* A = (mode < 3) ? Aext : g_att;
    float* C = (mode == 0) ? g_q : (mode == 1) ? g_k : (mode == 2) ? g_v : Cext;

    extern __shared__ float sm[];
    float (*AsH)[128][20] = reinterpret_cast<float(*)[128][20]>(sm);
    float (*AsL)[128][20] = reinterpret_cast<float(*)[128][20]>(sm + 2*128*20);
    float (*BsH)[16][136] = reinterpret_cast<float(*)[16][136]>(sm + 4*128*20);
    float (*BsL)[16][136] = reinterpret_cast<float(*)[16][136]>(sm + 4*128*20 + 2*16*136);

    const int tid  = threadIdx.x;
    const int lane = tid & 31;
    const int warp = tid >> 5;
    const int wm = warp & 3;           // 0..3 -> 32-row slices
    const int wn = warp >> 2;          // 0..1 -> 64-col slices
    const int cm = blockIdx.x * 128;
    const int cn = blockIdx.y * 128;
    const int rq = lane >> 2;          // 0..7
    const int cq = lane & 3;           // 0..3

    float4 ra[2], rb[2];

    // --- prologue: load tile 0 ---
    #pragma unroll
    for (int i = 0; i < 2; i++) {
        int idx = i * 256 + tid;
        int r = idx >> 2, cv = idx & 3;
        ra[i] = *reinterpret_cast<const float4*>(A + (size_t)(cm + r) * K + cv * 4);
    }
    #pragma unroll
    for (int i = 0; i < 2; i++) {
        int idx = i * 256 + tid;
        int r = idx >> 5, cv = idx & 31;
        rb[i] = *reinterpret_cast<const float4*>(W + (size_t)r * N + cn + cv * 4);
    }
    #pragma unroll
    for (int i = 0; i < 2; i++) {
        int idx = i * 256 + tid;
        int r = idx >> 2, cv = idx & 3;
        float4 h, l; split4(ra[i], h, l);
        *reinterpret_cast<float4*>(&AsH[0][r][cv * 4]) = h;
        *reinterpret_cast<float4*>(&AsL[0][r][cv * 4]) = l;
    }
    #pragma unroll
    for (int i = 0; i < 2; i++) {
        int idx = i * 256 + tid;
        int r = idx >> 5, cv = idx & 31;
        float4 h, l; split4(rb[i], h, l);
        *reinterpret_cast<float4*>(&BsH[0][r][cv * 4]) = h;
        *reinterpret_cast<float4*>(&BsL[0][r][cv * 4]) = l;
    }
    __syncthreads();

    float acc[2][8][4];
    #pragma unroll
    for (int mt = 0; mt < 2; mt++)
        #pragma unroll
        for (int nt = 0; nt < 8; nt++)
            #pragma unroll
            for (int j = 0; j < 4; j++) acc[mt][nt][j] = 0.f;

    const int NK = K / 16;  // 64
    for (int kt = 0; kt < NK; ++kt) {
        int cur = kt & 1;
        if (kt + 1 < NK) {
            int k0 = (kt + 1) * 16;
            #pragma unroll
            for (int i = 0; i < 2; i++) {
                int idx = i * 256 + tid;
                int r = idx >> 2, cv = idx & 3;
                ra[i] = *reinterpret_cast<const float4*>(A + (size_t)(cm + r) * K + k0 + cv * 4);
            }
            #pragma unroll
            for (int i = 0; i < 2; i++) {
                int idx = i * 256 + tid;
                int r = idx >> 5, cv = idx & 31;
                rb[i] = *reinterpret_cast<const float4*>(W + (size_t)(k0 + r) * N + cn + cv * 4);
            }
        }
        #pragma unroll
        for (int ks = 0; ks < 2; ++ks) {
            int k0 = ks * 8;
            float ah[2][4], al[2][4];
            #pragma unroll
            for (int mt = 0; mt < 2; mt++) {
                int r0 = wm * 32 + mt * 16 + rq;
                ah[mt][0] = AsH[cur][r0][k0 + cq];
                ah[mt][1] = AsH[cur][r0 + 8][k0 + cq];
                ah[mt][2] = AsH[cur][r0][k0 + cq + 4];
                ah[mt][3] = AsH[cur][r0 + 8][k0 + cq + 4];
                al[mt][0] = AsL[cur][r0][k0 + cq];
                al[mt][1] = AsL[cur][r0 + 8][k0 + cq];
                al[mt][2] = AsL[cur][r0][k0 + cq + 4];
                al[mt][3] = AsL[cur][r0 + 8][k0 + cq + 4];
            }
            float bh[8][2], bl[8][2];
            #pragma unroll
            for (int nt = 0; nt < 8; nt++) {
                int cc = wn * 64 + nt * 8 + rq;
                bh[nt][0] = BsH[cur][k0 + cq][cc];
                bh[nt][1] = BsH[cur][k0 + cq + 4][cc];
                bl[nt][0] = BsL[cur][k0 + cq][cc];
                bl[nt][1] = BsL[cur][k0 + cq + 4][cc];
            }
            #pragma unroll
            for (int mt = 0; mt < 2; mt++)
                #pragma unroll
                for (int nt = 0; nt < 8; nt++) {
                    mma_tf32(acc[mt][nt], ah[mt], bh[nt]);
                    mma_tf32(acc[mt][nt], al[mt], bh[nt]);
                    mma_tf32(acc[mt][nt], ah[mt], bl[nt]);
                }
        }
        if (kt + 1 < NK) {
            int nxt = cur ^ 1;
            #pragma unroll
            for (int i = 0; i < 2; i++) {
                int idx = i * 256 + tid;
                int r = idx >> 2, cv = idx & 3;
                float4 h, l; split4(ra[i], h, l);
                *reinterpret_cast<float4*>(&AsH[nxt][r][cv * 4]) = h;
                *reinterpret_cast<float4*>(&AsL[nxt][r][cv * 4]) = l;
            }
            #pragma unroll
            for (int i = 0; i < 2; i++) {
                int idx = i * 256 + tid;
                int r = idx >> 5, cv = idx & 31;
                float4 h, l; split4(rb[i], h, l);
                *reinterpret_cast<float4*>(&BsH[nxt][r][cv * 4]) = h;
                *reinterpret_cast<float4*>(&BsL[nxt][r][cv * 4]) = l;
            }
        }
        __syncthreads();
    }

    // --- epilogue: + bias, store ---
    #pragma unroll
    for (int mt = 0; mt < 2; mt++) {
        int r = cm + wm * 32 + mt * 16 + rq;
        #pragma unroll
        for (int nt = 0; nt < 8; nt++) {
            int c = cn + wn * 64 + nt * 8 + cq * 2;
            float b0 = bias[c], b1 = bias[c + 1];
            *reinterpret_cast<float2*>(C + (size_t)r * N + c) =
                make_float2(acc[mt][nt][0] + b0, acc[mt][nt][1] + b1);
            *reinterpret_cast<float2*>(C + (size_t)(r + 8) * N + c) =
                make_float2(acc[mt][nt][2] + b0, acc[mt][nt][3] + b1);
        }
    }
}

// ---------------------------------------------------------------------------
// Flash attention (causal + key padding), 3xTF32 for QK^T and P*V.
// Grid: (S/64, B*H). 128 threads = 4 warps; warp w owns query rows [w*16, w*16+16).
// ---------------------------------------------------------------------------
// smem floats: QsH,QsL,KsH,KsL,PsH,PsL = 6*64*68 ; VsH,VsL = 2*64*72 ; Ms 64
#define FL_Q  (64 * 68)
#define FL_V  (64 * 72)
#define FLASH_SMEM ((6 * FL_Q + 2 * FL_V + 64) * 4)   // 141568 bytes

__global__ __launch_bounds__(128)
void flash_attn_kernel(const int* __restrict__ pmask)
{
    extern __shared__ float smem[];
    float (*QsH)[68] = reinterpret_cast<float(*)[68]>(smem);
    float (*QsL)[68] = reinterpret_cast<float(*)[68]>(smem + FL_Q);
    float (*KsH)[68] = reinterpret_cast<float(*)[68]>(smem + 2 * FL_Q);
    float (*KsL)[68] = reinterpret_cast<float(*)[68]>(smem + 3 * FL_Q);
    float (*PsH)[68] = reinterpret_cast<float(*)[68]>(smem + 4 * FL_Q);
    float (*PsL)[68] = reinterpret_cast<float(*)[68]>(smem + 5 * FL_Q);
    float (*VsH)[72] = reinterpret_cast<float(*)[72]>(smem + 6 * FL_Q);
    float (*VsL)[72] = reinterpret_cast<float(*)[72]>(smem + 6 * FL_Q + FL_V);
    int* Ms = reinterpret_cast<int*>(smem + 6 * FL_Q + 2 * FL_V);

    const int tid = threadIdx.x, lane = tid & 31, warp = tid >> 5;
    const int qb = blockIdx.x;                 // query block 0..31
    const int bh = blockIdx.y;                 // 0..63
    const int b = bh >> 4, h = bh & 15;
    const size_t head_off = ((size_t)b * SS) * DD + (size_t)h * DHH;
    const float* qp = g_q + head_off;
    const float* kp = g_k + head_off;
    const float* vp = g_v + head_off;

    const int rq = lane >> 2;   // 0..7
    const int cq = lane & 3;    // 0..3
    const int row0 = warp * 16 + rq;

    // Load Q tile [64 x 64], split hi/lo
    #pragma unroll
    for (int i = 0; i < 8; i++) {
        int idx = i * 128 + tid;
        int r = idx >> 4, c4 = idx & 15;
        float4 v = *reinterpret_cast<const float4*>(qp + (size_t)(qb * 64 + r) * DD + c4 * 4);
        float4 hh, ll; split4(v, hh, ll);
        *reinterpret_cast<float4*>(&QsH[r][c4 * 4]) = hh;
        *reinterpret_cast<float4*>(&QsL[r][c4 * 4]) = ll;
    }

    float o[8][4];
    #pragma unroll
    for (int nt = 0; nt < 8; nt++)
        #pragma unroll
        for (int j = 0; j < 4; j++) o[nt][j] = 0.f;
    float m0 = -1e30f, m1 = -1e30f, l0 = 0.f, l1 = 0.f;

    for (int kb = 0; kb <= qb; ++kb) {
        __syncthreads();   // protects Qs (first iter) + Ks/Vs reuse (later iters)
        #pragma unroll
        for (int i = 0; i < 8; i++) {
            int idx = i * 128 + tid;
            int r = idx >> 4, c4 = idx & 15;
            float4 kv = *reinterpret_cast<const float4*>(kp + (size_t)(kb * 64 + r) * DD + c4 * 4);
            float4 vv = *reinterpret_cast<const float4*>(vp + (size_t)(kb * 64 + r) * DD + c4 * 4);
            float4 hh, ll;
            split4(kv, hh, ll);
            *reinterpret_cast<float4*>(&KsH[r][c4 * 4]) = hh;
            *reinterpret_cast<float4*>(&KsL[r][c4 * 4]) = ll;
            split4(vv, hh, ll);
            *reinterpret_cast<float4*>(&VsH[r][c4 * 4]) = hh;
            *reinterpret_cast<float4*>(&VsL[r][c4 * 4]) = ll;
        }
        if (tid < 64) Ms[tid] = pmask[b * SS + kb * 64 + tid];
        __syncthreads();

        // --- S = Q * K^T (warp: 16 x 64), 3xTF32 ---
        float sc[8][4];
        #pragma unroll
        for (int nt = 0; nt < 8; nt++)
            #pragma unroll
            for (int j = 0; j < 4; j++) sc[nt][j] = 0.f;

        #pragma unroll
        for (int ks = 0; ks < 8; ++ks) {
            int k0 = ks * 8;
            float ah[4], al[4];
            ah[0] = QsH[row0][k0 + cq];
            ah[1] = QsH[row0 + 8][k0 + cq];
            ah[2] = QsH[row0][k0 + cq + 4];
            ah[3] = QsH[row0 + 8][k0 + cq + 4];
            al[0] = QsL[row0][k0 + cq];
            al[1] = QsL[row0 + 8][k0 + cq];
            al[2] = QsL[row0][k0 + cq + 4];
            al[3] = QsL[row0 + 8][k0 + cq + 4];
            #pragma unroll
            for (int nt = 0; nt < 8; nt++) {
                int n = nt * 8 + rq;
                float bh[2], bl[2];
                bh[0] = KsH[n][k0 + cq];
                bh[1] = KsH[n][k0 + cq + 4];
                bl[0] = KsL[n][k0 + cq];
                bl[1] = KsL[n][k0 + cq + 4];
                mma_tf32(sc[nt], ah, bh);
                mma_tf32(sc[nt], al, bh);
                mma_tf32(sc[nt], ah, bl);
            }
        }

        // --- mask + scale (sentinel -1e30 avoids inf-inf NaN) ---
        const int gm0 = qb * 64 + row0, gm1 = gm0 + 8;
        #pragma unroll
        for (int nt = 0; nt < 8; nt++) {
            int nloc = nt * 8 + cq * 2;
            int gn = kb * 64 + nloc;
            #pragma unroll
            for (int j = 0; j < 2; j++) {
                bool pv = (Ms[nloc + j] != 0);
                sc[nt][j]     = (pv && (gn + j) <= gm0) ? sc[nt][j] * INV_SCALE     : -1e30f;
                sc[nt][2 + j] = (pv && (gn + j) <= gm1) ? sc[nt][2 + j] * INV_SCALE : -1e30f;
            }
        }

        // --- online softmax ---
        float mx0 = -1e30f, mx1 = -1e30f;
        #pragma unroll
        for (int nt = 0; nt < 8; nt++) {
            mx0 = fmaxf(mx0, fmaxf(sc[nt][0], sc[nt][1]));
            mx1 = fmaxf(mx1, fmaxf(sc[nt][2], sc[nt][3]));
        }
        mx0 = fmaxf(mx0, __shfl_xor_sync(0xffffffffu, mx0, 1));
        mx0 = fmaxf(mx0, __shfl_xor_sync(0xffffffffu, mx0, 2));
        mx1 = fmaxf(mx1, __shfl_xor_sync(0xffffffffu, mx1, 1));
        mx1 = fmaxf(mx1, __shfl_xor_sync(0xffffffffu, mx1, 2));

        float mn0 = fmaxf(m0, mx0), mn1 = fmaxf(m1, mx1);
        float al0 = exp2f((m0 - mn0) * LOG2E);
        float al1 = exp2f((m1 - mn1) * LOG2E);

        float s0 = 0.f, s1 = 0.f;
        #pragma unroll
        for (int nt = 0; nt < 8; nt++) {
            float p00 = exp2f((sc[nt][0] - mn0) * LOG2E);
            float p01 = exp2f((sc[nt][1] - mn0) * LOG2E);
            float p10 = exp2f((sc[nt][2] - mn1) * LOG2E);
            float p11 = exp2f((sc[nt][3] - mn1) * LOG2E);
            s0 += p00 + p01;
            s1 += p10 + p11;
            int nloc = nt * 8 + cq * 2;
            float h00, l00, h01, l01, h10, l10, h11, l11;
            tf32split(p00, h00, l00);
            tf32split(p01, h01, l01);
            tf32split(p10, h10, l10);
            tf32split(p11, h11, l11);
            *reinterpret_cast<float2*>(&PsH[row0][nloc])     = make_float2(h00, h01);
            *reinterpret_cast<float2*>(&PsL[row0][nloc])     = make_float2(l00, l01);
            *reinterpret_cast<float2*>(&PsH[row0 + 8][nloc]) = make_float2(h10, h11);
            *reinterpret_cast<float2*>(&PsL[row0 + 8][nloc]) = make_float2(l10, l11);
        }
        s0 += __shfl_xor_sync(0xffffffffu, s0, 1);
        s0 += __shfl_xor_sync(0xffffffffu, s0, 2);
        s1 += __shfl_xor_sync(0xffffffffu, s1, 1);
        s1 += __shfl_xor_sync(0xffffffffu, s1, 2);

        l0 = l0 * al0 + s0;
        l1 = l1 * al1 + s1;
        m0 = mn0; m1 = mn1;

        #pragma unroll
        for (int nt = 0; nt < 8; nt++) {
            o[nt][0] *= al0; o[nt][1] *= al0;
            o[nt][2] *= al1; o[nt][3] *= al1;
        }
        __syncwarp();   // warp-private Ps rows: write->read ordering

        // --- O += P * V, 3xTF32 ---
        #pragma unroll
        for (int ks = 0; ks < 8; ++ks) {
            int k0 = ks * 8;
            float ah[4], al[4];
            ah[0] = PsH[row0][k0 + cq];
            ah[1] = PsH[row0 + 8][k0 + cq];
            ah[2] = PsH[row0][k0 + cq + 4];
            ah[3] = PsH[row0 + 8][k0 + cq + 4];
            al[0] = PsL[row0][k0 + cq];
            al[1] = PsL[row0 + 8][k0 + cq];
            al[2] = PsL[row0][k0 + cq + 4];
            al[3] = PsL[row0 + 8][k0 + cq + 4];
            #pragma unroll
            for (int nt = 0; nt < 8; nt++) {
                int n = nt * 8 + rq;
                float bh[2], bl[2];
                bh[0] = VsH[k0 + cq][n];
                bh[1] = VsH[k0 + cq + 4][n];
                bl[0] = VsL[k0 + cq][n];
                bl[1] = VsL[k0 + cq + 4][n];
                mma_tf32(o[nt], ah, bh);
                mma_tf32(o[nt], al, bh);
                mma_tf32(o[nt], ah, bl);
            }
        }
    }

    // --- epilogue: normalize, store to g_att [b, s, h, dh] ---
    float i0 = (l0 > 0.f) ? 1.f / l0 : 0.f;
    float i1 = (l1 > 0.f) ? 1.f / l1 : 0.f;
    float* op = g_att + head_off + (size_t)(qb * 64) * DD;
    #pragma unroll
    for (int nt = 0; nt < 8; nt++) {
        int c = nt * 8 + cq * 2;
        *reinterpret_cast<float2*>(op + (size_t)row0 * DD + c) =
            make_float2(o[nt][0] * i0, o[nt][1] * i0);
        *reinterpret_cast<float2*>(op + (size_t)(row0 + 8) * DD + c) =
            make_float2(o[nt][2] * i1, o[nt][3] * i1);
    }
}

// ---------------------------------------------------------------------------
extern "C" void kernel_launch(void* const* d_in, const int* in_sizes, int n_in,
                              void* d_out, int out_size)
{
    (void)in_sizes; (void)n_in; (void)out_size;
    const float* x  = (const float*)d_in[0];
    const float* Wq = (const float*)d_in[1];
    const float* bq = (const float*)d_in[2];
    const float* Wk = (const float*)d_in[3];
    const float* bk = (const float*)d_in[4];
    const float* Wv = (const float*)d_in[5];
    const float* bv = (const float*)d_in[6];
    const float* Wo = (const float*)d_in[7];
    const float* bo = (const float*)d_in[8];
    const int*   pm = (const int*)d_in[9];
    float* out = (float*)d_out;

    cudaFuncSetAttribute(gemm_bias_3xtf32,
                         cudaFuncAttributeMaxDynamicSharedMemorySize, GEMM_SMEM);
    cudaFuncSetAttribute(flash_attn_kernel,
                         cudaFuncAttributeMaxDynamicSharedMemorySize, FLASH_SMEM);

    dim3 ggrid(BSROWS / 128, DD / 128);   // (64, 8)
    gemm_bias_3xtf32<<<ggrid, 256, GEMM_SMEM>>>(x, Wq, bq, nullptr, 0);
    gemm_bias_3xtf32<<<ggrid, 256, GEMM_SMEM>>>(x, Wk, bk, nullptr, 1);
    gemm_bias_3xtf32<<<ggrid, 256, GEMM_SMEM>>>(x, Wv, bv, nullptr, 2);

    dim3 fgrid(SS / 64, BB * HH);         // (32, 64)
    flash_attn_kernel<<<fgrid, 128, FLASH_SMEM>>>(pm);

    gemm_bias_3xtf32<<<ggrid, 256, GEMM_SMEM>>>(nullptr, Wo, bo, out, 3);
}

// round 3
// speedup vs baseline: 2.2360x; 2.2360x over previous
#include <cuda_runtime.h>
#include <cuda_bf16.h>
#include <cstdint>

// Problem constants
#define BB 4
#define SS 2048
#define DD 1024
#define HH 16
#define DHH 64
#define BSROWS (BB * SS)          // 8192

typedef __nv_bfloat16 bf16;

// ---------------------------------------------------------------------------
// Device-global scratch (allocation-free). All pre-split bf16 hi/mid pairs.
// ---------------------------------------------------------------------------
__device__ bf16 g_xh[(size_t)BSROWS * DD], g_xm[(size_t)BSROWS * DD];
__device__ bf16 g_qh[(size_t)BSROWS * DD], g_qm[(size_t)BSROWS * DD];
__device__ bf16 g_kh[(size_t)BSROWS * DD], g_km[(size_t)BSROWS * DD];
__device__ bf16 g_vh[(size_t)BSROWS * DD], g_vm[(size_t)BSROWS * DD];
__device__ bf16 g_ah[(size_t)BSROWS * DD], g_am[(size_t)BSROWS * DD];
__device__ bf16 g_wth[4 * (size_t)DD * DD], g_wtm[4 * (size_t)DD * DD];  // W^T [n][k]

#define LOG2E 1.4426950408889634f

// ---------------------------------------------------------------------------
// Helpers
// ---------------------------------------------------------------------------
__device__ __forceinline__ void mma_bf16(float* c, const unsigned* a, const unsigned* b) {
    asm volatile(
        "mma.sync.aligned.m16n8k16.row.col.f32.bf16.bf16.f32 "
        "{%0,%1,%2,%3}, {%4,%5,%6,%7}, {%8,%9}, {%0,%1,%2,%3};\n"
        : "+f"(c[0]), "+f"(c[1]), "+f"(c[2]), "+f"(c[3])
        : "r"(a[0]), "r"(a[1]), "r"(a[2]), "r"(a[3]),
          "r"(b[0]), "r"(b[1]));
}

__device__ __forceinline__ unsigned pack2(bf16 lo, bf16 hi) {
    unsigned l = __bfloat16_as_ushort(lo), h = __bfloat16_as_ushort(hi);
    return l | (h << 16);
}

__device__ __forceinline__ void bsplit(float x, bf16& h, bf16& m) {
    h = __float2bfloat16_rn(x);
    m = __float2bfloat16_rn(x - __bfloat162float(h));
}

// pack hi of (x,y); return mid pack via out-param
__device__ __forceinline__ unsigned packHM(float x, float y, unsigned& mp) {
    bf16 hx, mx, hy, my;
    bsplit(x, hx, mx);
    bsplit(y, hy, my);
    mp = pack2(mx, my);
    return pack2(hx, hy);
}

__device__ __forceinline__ void cpa16(void* s, const void* g) {
    unsigned sa = (unsigned)__cvta_generic_to_shared(s);
    asm volatile("cp.async.cg.shared.global [%0], [%1], 16;\n" :: "r"(sa), "l"(g));
}
__device__ __forceinline__ void cpa_commit() {
    asm volatile("cp.async.commit_group;\n");
}
template <int N>
__device__ __forceinline__ void cpa_wait() {
    asm volatile("cp.async.wait_group %0;\n" :: "n"(N));
}

// ---------------------------------------------------------------------------
// Prep: split x (fp32 -> bf16 hi/mid)
// ---------------------------------------------------------------------------
__global__ __launch_bounds__(256)
void split_src(const float* __restrict__ x)
{
    int i = blockIdx.x * 256 + threadIdx.x;            // over float4s: 2M
    float4 v = reinterpret_cast<const float4*>(x)[i];
    bf16 h0, m0, h1, m1, h2, m2, h3, m3;
    bsplit(v.x, h0, m0); bsplit(v.y, h1, m1);
    bsplit(v.z, h2, m2); bsplit(v.w, h3, m3);
    uint2 uh, um;
    uh.x = pack2(h0, h1); uh.y = pack2(h2, h3);
    um.x = pack2(m0, m1); um.y = pack2(m2, m3);
    reinterpret_cast<uint2*>(g_xh)[i] = uh;
    reinterpret_cast<uint2*>(g_xm)[i] = um;
}

// ---------------------------------------------------------------------------
// Prep: transpose + split W [k][n] fp32 -> g_wt{h,m}[widx] as [n][k] bf16
// ---------------------------------------------------------------------------
__global__ __launch_bounds__(256)
void wsplit(const float* __restrict__ W, int widx)
{
    __shared__ float t[32][33];
    const int kb = blockIdx.x * 32, nb = blockIdx.y * 32;
    const int r = threadIdx.x >> 3, c4 = (threadIdx.x & 7) * 4;
    float4 v = *reinterpret_cast<const float4*>(W + (size_t)(kb + r) * DD + nb + c4);
    t[r][c4 + 0] = v.x; t[r][c4 + 1] = v.y; t[r][c4 + 2] = v.z; t[r][c4 + 3] = v.w;
    __syncthreads();
    bf16* oh = g_wth + (size_t)widx * DD * DD;
    bf16* om = g_wtm + (size_t)widx * DD * DD;
    bf16 h[4], m[4];
    #pragma unroll
    for (int j = 0; j < 4; j++) bsplit(t[c4 + j][r], h[j], m[j]);
    uint2 uh, um;
    uh.x = pack2(h[0], h[1]); uh.y = pack2(h[2], h[3]);
    um.x = pack2(m[0], m[1]); um.y = pack2(m[2], m[3]);
    size_t o = (size_t)(nb + r) * DD + kb + c4;
    *reinterpret_cast<uint2*>(oh + o) = uh;
    *reinterpret_cast<uint2*>(om + o) = um;
}

// ---------------------------------------------------------------------------
// GEMM (3xBF16, m16n8k16): C[M,N] = A * W + bias, M=8192, N=K=1024
// CTA tile 128x128, kstep 32, 256 threads (8 warps: 4 M x 2 N), cp.async dbuf.
// mode -1: md=blockIdx.z (QKV, A=g_x, out bf16 split to g_{q,k,v}, q scaled 1/8)
// mode  3: A=g_a (attended), out fp32 to outF
// ---------------------------------------------------------------------------
#define KS 32
#define AST 40
#define SLAB (2 * 128 * AST)                 // halves per (dbuf) array
#define GEMM_SMEM (4 * SLAB * 2)             // 81920 bytes

__global__ __launch_bounds__(256, 2)
void gemm_k(const float* __restrict__ b0, const float* __restrict__ b1,
            const float* __restrict__ b2, float* __restrict__ outF, int mode)
{
    const int md = (mode < 0) ? (int)blockIdx.z : mode;
    const bf16* Ah = (md < 3) ? g_xh : g_ah;
    const bf16* Am = (md < 3) ? g_xm : g_am;
    const bf16* Wh = g_wth + (size_t)md * DD * DD;
    const bf16* Wm = g_wtm + (size_t)md * DD * DD;
    const float* bias = (md == 1) ? b1 : (md == 2) ? b2 : b0;
    const float scale = (md == 0) ? 0.125f : 1.0f;
    bf16* OH = (md == 0) ? g_qh : (md == 1) ? g_kh : g_vh;
    bf16* OM = (md == 0) ? g_qm : (md == 1) ? g_km : g_vm;

    extern __shared__ bf16 sm[];
    bf16* sAh = sm;
    bf16* sAm = sm + SLAB;
    bf16* sBh = sm + 2 * SLAB;
    bf16* sBm = sm + 3 * SLAB;

    const int tid  = threadIdx.x;
    const int lane = tid & 31;
    const int warp = tid >> 5;
    const int wm = warp & 3, wn = warp >> 2;
    const int cm = blockIdx.x * 128, cn = blockIdx.y * 128;
    const int rq = lane >> 2, cq = lane & 3;

    // issue stage kt into buffer buf
    auto issue = [&](int kt, int buf) {
        const int k0 = kt * KS;
        #pragma unroll
        for (int i = 0; i < 2; i++) {
            int idx = i * 256 + tid;
            int r = idx >> 2, c8 = (idx & 3) * 8;
            size_t ga = (size_t)(cm + r) * DD + k0 + c8;
            size_t gb = (size_t)(cn + r) * DD + k0 + c8;
            int so = buf * 128 * AST + r * AST + c8;
            cpa16(&sAh[so], Ah + ga);
            cpa16(&sAm[so], Am + ga);
            cpa16(&sBh[so], Wh + gb);
            cpa16(&sBm[so], Wm + gb);
        }
        cpa_commit();
    };

    float acc[2][8][4];
    #pragma unroll
    for (int mt = 0; mt < 2; mt++)
        #pragma unroll
        for (int nt = 0; nt < 8; nt++)
            #pragma unroll
            for (int j = 0; j < 4; j++) acc[mt][nt][j] = 0.f;

    const int NK = DD / KS;  // 32
    issue(0, 0);

    for (int kt = 0; kt < NK; ++kt) {
        int cur = kt & 1;
        if (kt + 1 < NK) { issue(kt + 1, cur ^ 1); cpa_wait<1>(); }
        else             { cpa_wait<0>(); }
        __syncthreads();

        #pragma unroll
        for (int ch = 0; ch < 2; ++ch) {
            const int kc = ch * 16;
            unsigned ah[2][4], am[2][4];
            #pragma unroll
            for (int mt = 0; mt < 2; mt++) {
                int r0 = wm * 32 + mt * 16 + rq;
                int base = cur * 128 * AST;
                ah[mt][0] = *reinterpret_cast<const unsigned*>(&sAh[base + r0 * AST + kc + 2 * cq]);
                ah[mt][1] = *reinterpret_cast<const unsigned*>(&sAh[base + (r0 + 8) * AST + kc + 2 * cq]);
                ah[mt][2] = *reinterpret_cast<const unsigned*>(&sAh[base + r0 * AST + kc + 2 * cq + 8]);
                ah[mt][3] = *reinterpret_cast<const unsigned*>(&sAh[base + (r0 + 8) * AST + kc + 2 * cq + 8]);
                am[mt][0] = *reinterpret_cast<const unsigned*>(&sAm[base + r0 * AST + kc + 2 * cq]);
                am[mt][1] = *reinterpret_cast<const unsigned*>(&sAm[base + (r0 + 8) * AST + kc + 2 * cq]);
                am[mt][2] = *reinterpret_cast<const unsigned*>(&sAm[base + r0 * AST + kc + 2 * cq + 8]);
                am[mt][3] = *reinterpret_cast<const unsigned*>(&sAm[base + (r0 + 8) * AST + kc + 2 * cq + 8]);
            }
            #pragma unroll
            for (int nt = 0; nt < 8; nt++) {
                int n = wn * 64 + nt * 8 + rq;
                int base = cur * 128 * AST + n * AST + kc + 2 * cq;
                unsigned bh[2], bm[2];
                bh[0] = *reinterpret_cast<const unsigned*>(&sBh[base]);
                bh[1] = *reinterpret_cast<const unsigned*>(&sBh[base + 8]);
                bm[0] = *reinterpret_cast<const unsigned*>(&sBm[base]);
                bm[1] = *reinterpret_cast<const unsigned*>(&sBm[base + 8]);
                #pragma unroll
                for (int mt = 0; mt < 2; mt++) {
                    mma_bf16(acc[mt][nt], ah[mt], bh);
                    mma_bf16(acc[mt][nt], am[mt], bh);
                    mma_bf16(acc[mt][nt], ah[mt], bm);
                }
            }
        }
        __syncthreads();
    }

    // epilogue
    #pragma unroll
    for (int mt = 0; mt < 2; mt++) {
        int r = cm + wm * 32 + mt * 16 + rq;
        #pragma unroll
        for (int nt = 0; nt < 8; nt++) {
            int c = cn + wn * 64 + nt * 8 + cq * 2;
            float bb0 = bias[c], bb1 = bias[c + 1];
            float v0 = (acc[mt][nt][0] + bb0) * scale;
            float v1 = (acc[mt][nt][1] + bb1) * scale;
            float v2 = (acc[mt][nt][2] + bb0) * scale;
            float v3 = (acc[mt][nt][3] + bb1) * scale;
            if (md == 3) {
                *reinterpret_cast<float2*>(outF + (size_t)r * DD + c) = make_float2(v0, v1);
                *reinterpret_cast<float2*>(outF + (size_t)(r + 8) * DD + c) = make_float2(v2, v3);
            } else {
                bf16 h0, m0, h1, m1;
                bsplit(v0, h0, m0); bsplit(v1, h1, m1);
                *reinterpret_cast<unsigned*>(OH + (size_t)r * DD + c) = pack2(h0, h1);
                *reinterpret_cast<unsigned*>(OM + (size_t)r * DD + c) = pack2(m0, m1);
                bsplit(v2, h0, m0); bsplit(v3, h1, m1);
                *reinterpret_cast<unsigned*>(OH + (size_t)(r + 8) * DD + c) = pack2(h0, h1);
                *reinterpret_cast<unsigned*>(OM + (size_t)(r + 8) * DD + c) = pack2(m0, m1);
            }
        }
    }
}

// ---------------------------------------------------------------------------
// Flash attention (causal + key padding), 3xBF16 m16n8k16.
// Grid: (S/64, B*H), 128 threads = 4 warps; warp w owns query rows [16w,16w+16).
// Q pre-scaled by 1/8 in GEMM epilogue. P stays in registers (FA2 layout trick).
// ---------------------------------------------------------------------------
#define FST 72                                // smem k-stride (halves)
#define FQ  (64 * FST)                        // 4608 halves per array
#define FLASH_SMEM (6 * FQ * 2 + 64 * 4)      // 55552 bytes

__global__ __launch_bounds__(128, 3)
void flash_attn_kernel(const int* __restrict__ pmask)
{
    extern __shared__ bf16 fsm[];
    bf16* QH = fsm;
    bf16* QM = fsm + FQ;
    bf16* KH = fsm + 2 * FQ;
    bf16* KM = fsm + 3 * FQ;
    bf16* VH = fsm + 4 * FQ;
    bf16* VM = fsm + 5 * FQ;
    int* Ms = reinterpret_cast<int*>(fsm + 6 * FQ);

    const int tid = threadIdx.x, lane = tid & 31, warp = tid >> 5;
    const int qb = (int)(gridDim.x - 1) - (int)blockIdx.x;  // heavy blocks first
    const int bh = blockIdx.y;
    const int b = bh >> 4, h = bh & 15;
    const size_t head_off = ((size_t)b * SS) * DD + (size_t)h * DHH;

    const int rq = lane >> 2, cq = lane & 3;
    const int row0 = warp * 16 + rq;

    // Q tile [64 x 64] hi/mid via cp.async
    #pragma unroll
    for (int i = 0; i < 4; i++) {
        int idx = i * 128 + tid;
        int r = idx >> 3, c8 = (idx & 7) * 8;
        size_t g = head_off + (size_t)(qb * 64 + r) * DD + c8;
        cpa16(&QH[r * FST + c8], g_qh + g);
        cpa16(&QM[r * FST + c8], g_qm + g);
    }
    cpa_commit();

    float o[8][4];
    #pragma unroll
    for (int nt = 0; nt < 8; nt++)
        #pragma unroll
        for (int j = 0; j < 4; j++) o[nt][j] = 0.f;
    float m0 = -1e30f, m1 = -1e30f, l0 = 0.f, l1 = 0.f;

    for (int kb = 0; kb <= qb; ++kb) {
        __syncthreads();   // smem reuse from previous iteration
        #pragma unroll
        for (int i = 0; i < 4; i++) {
            int idx = i * 128 + tid;
            int r = idx >> 3, c8 = (idx & 7) * 8;
            size_t g = head_off + (size_t)(kb * 64 + r) * DD + c8;
            cpa16(&KH[r * FST + c8], g_kh + g);
            cpa16(&KM[r * FST + c8], g_km + g);
            cpa16(&VH[r * FST + c8], g_vh + g);
            cpa16(&VM[r * FST + c8], g_vm + g);
        }
        cpa_commit();
        if (tid < 64) Ms[tid] = pmask[b * SS + kb * 64 + tid];
        cpa_wait<0>();
        __syncthreads();

        // --- S = Q K^T (warp: 16 x 64), 3xBF16 ---
        float sc[8][4];
        #pragma unroll
        for (int nt = 0; nt < 8; nt++)
            #pragma unroll
            for (int j = 0; j < 4; j++) sc[nt][j] = 0.f;

        #pragma unroll
        for (int ch = 0; ch < 4; ++ch) {
            const int kc = ch * 16;
            unsigned ah[4], am[4];
            ah[0] = *reinterpret_cast<const unsigned*>(&QH[row0 * FST + kc + 2 * cq]);
            ah[1] = *reinterpret_cast<const unsigned*>(&QH[(row0 + 8) * FST + kc + 2 * cq]);
            ah[2] = *reinterpret_cast<const unsigned*>(&QH[row0 * FST + kc + 2 * cq + 8]);
            ah[3] = *reinterpret_cast<const unsigned*>(&QH[(row0 + 8) * FST + kc + 2 * cq + 8]);
            am[0] = *reinterpret_cast<const unsigned*>(&QM[row0 * FST + kc + 2 * cq]);
            am[1] = *reinterpret_cast<const unsigned*>(&QM[(row0 + 8) * FST + kc + 2 * cq]);
            am[2] = *reinterpret_cast<const unsigned*>(&QM[row0 * FST + kc + 2 * cq + 8]);
            am[3] = *reinterpret_cast<const unsigned*>(&QM[(row0 + 8) * FST + kc + 2 * cq + 8]);
            #pragma unroll
            for (int nt = 0; nt < 8; nt++) {
                int n = nt * 8 + rq;
                int base = n * FST + kc + 2 * cq;
                unsigned bhf[2], bmf[2];
                bhf[0] = *reinterpret_cast<const unsigned*>(&KH[base]);
                bhf[1] = *reinterpret_cast<const unsigned*>(&KH[base + 8]);
                bmf[0] = *reinterpret_cast<const unsigned*>(&KM[base]);
                bmf[1] = *reinterpret_cast<const unsigned*>(&KM[base + 8]);
                mma_bf16(sc[nt], ah, bhf);
                mma_bf16(sc[nt], am, bhf);
                mma_bf16(sc[nt], ah, bmf);
            }
        }

        // --- mask (Q already scaled; sentinel -1e30) ---
        const int gm0 = qb * 64 + row0, gm1 = gm0 + 8;
        #pragma unroll
        for (int nt = 0; nt < 8; nt++) {
            int nloc = nt * 8 + cq * 2;
            int gn = kb * 64 + nloc;
            #pragma unroll
            for (int j = 0; j < 2; j++) {
                bool pv = (Ms[nloc + j] != 0);
                sc[nt][j]     = (pv && (gn + j) <= gm0) ? sc[nt][j]     : -1e30f;
                sc[nt][2 + j] = (pv && (gn + j) <= gm1) ? sc[nt][2 + j] : -1e30f;
            }
        }

        // --- online softmax (p written back into sc) ---
        float mx0 = -1e30f, mx1 = -1e30f;
        #pragma unroll
        for (int nt = 0; nt < 8; nt++) {
            mx0 = fmaxf(mx0, fmaxf(sc[nt][0], sc[nt][1]));
            mx1 = fmaxf(mx1, fmaxf(sc[nt][2], sc[nt][3]));
        }
        mx0 = fmaxf(mx0, __shfl_xor_sync(0xffffffffu, mx0, 1));
        mx0 = fmaxf(mx0, __shfl_xor_sync(0xffffffffu, mx0, 2));
        mx1 = fmaxf(mx1, __shfl_xor_sync(0xffffffffu, mx1, 1));
        mx1 = fmaxf(mx1, __shfl_xor_sync(0xffffffffu, mx1, 2));

        float mn0 = fmaxf(m0, mx0), mn1 = fmaxf(m1, mx1);
        float al0 = exp2f((m0 - mn0) * LOG2E);
        float al1 = exp2f((m1 - mn1) * LOG2E);

        float s0 = 0.f, s1 = 0.f;
        #pragma unroll
        for (int nt = 0; nt < 8; nt++) {
            sc[nt][0] = exp2f((sc[nt][0] - mn0) * LOG2E);
            sc[nt][1] = exp2f((sc[nt][1] - mn0) * LOG2E);
            sc[nt][2] = exp2f((sc[nt][2] - mn1) * LOG2E);
            sc[nt][3] = exp2f((sc[nt][3] - mn1) * LOG2E);
            s0 += sc[nt][0] + sc[nt][1];
            s1 += sc[nt][2] + sc[nt][3];
        }
        s0 += __shfl_xor_sync(0xffffffffu, s0, 1);
        s0 += __shfl_xor_sync(0xffffffffu, s0, 2);
        s1 += __shfl_xor_sync(0xffffffffu, s1, 1);
        s1 += __shfl_xor_sync(0xffffffffu, s1, 2);

        l0 = l0 * al0 + s0;
        l1 = l1 * al1 + s1;
        m0 = mn0; m1 = mn1;

        #pragma unroll
        for (int nt = 0; nt < 8; nt++) {
            o[nt][0] *= al0; o[nt][1] *= al0;
            o[nt][2] *= al1; o[nt][3] *= al1;
        }

        // --- O += P V: A-frags packed straight from S registers (FA2 trick) ---
        #pragma unroll
        for (int ch = 0; ch < 4; ++ch) {
            const int kc = ch * 16;
            const int t0 = 2 * ch, t1 = 2 * ch + 1;
            unsigned ah[4], am[4];
            ah[0] = packHM(sc[t0][0], sc[t0][1], am[0]);
            ah[1] = packHM(sc[t0][2], sc[t0][3], am[1]);
            ah[2] = packHM(sc[t1][0], sc[t1][1], am[2]);
            ah[3] = packHM(sc[t1][2], sc[t1][3], am[3]);
            #pragma unroll
            for (int nt = 0; nt < 8; nt++) {
                int n = nt * 8 + rq;
                unsigned bhf[2], bmf[2];
                bhf[0] = pack2(VH[(kc + 2 * cq) * FST + n],     VH[(kc + 2 * cq + 1) * FST + n]);
                bhf[1] = pack2(VH[(kc + 2 * cq + 8) * FST + n], VH[(kc + 2 * cq + 9) * FST + n]);
                bmf[0] = pack2(VM[(kc + 2 * cq) * FST + n],     VM[(kc + 2 * cq + 1) * FST + n]);
                bmf[1] = pack2(VM[(kc + 2 * cq + 8) * FST + n], VM[(kc + 2 * cq + 9) * FST + n]);
                mma_bf16(o[nt], ah, bhf);
                mma_bf16(o[nt], am, bhf);
                mma_bf16(o[nt], ah, bmf);
            }
        }
    }

    // --- epilogue: normalize, split, store to g_a{h,m} [b, s, h, dh] ---
    float i0 = (l0 > 0.f) ? 1.f / l0 : 0.f;
    float i1 = (l1 > 0.f) ? 1.f / l1 : 0.f;
    size_t ob = head_off + (size_t)(qb * 64) * DD;
    #pragma unroll
    for (int nt = 0; nt < 8; nt++) {
        int c = nt * 8 + cq * 2;
        bf16 h0, mm0, h1, mm1;
        bsplit(o[nt][0] * i0, h0, mm0); bsplit(o[nt][1] * i0, h1, mm1);
        *reinterpret_cast<unsigned*>(g_ah + ob + (size_t)row0 * DD + c) = pack2(h0, h1);
        *reinterpret_cast<unsigned*>(g_am + ob + (size_t)row0 * DD + c) = pack2(mm0, mm1);
        bsplit(o[nt][2] * i1, h0, mm0); bsplit(o[nt][3] * i1, h1, mm1);
        *reinterpret_cast<unsigned*>(g_ah + ob + (size_t)(row0 + 8) * DD + c) = pack2(h0, h1);
        *reinterpret_cast<unsigned*>(g_am + ob + (size_t)(row0 + 8) * DD + c) = pack2(mm0, mm1);
    }
}

// ---------------------------------------------------------------------------
extern "C" void kernel_launch(void* const* d_in, const int* in_sizes, int n_in,
                              void* d_out, int out_size)
{
    (void)in_sizes; (void)n_in; (void)out_size;
    const float* x  = (const float*)d_in[0];
    const float* Wq = (const float*)d_in[1];
    const float* bq = (const float*)d_in[2];
    const float* Wk = (const float*)d_in[3];
    const float* bk = (const float*)d_in[4];
    const float* Wv = (const float*)d_in[5];
    const float* bv = (const float*)d_in[6];
    const float* Wo = (const float*)d_in[7];
    const float* bo = (const float*)d_in[8];
    const int*   pm = (const int*)d_in[9];
    float* out = (float*)d_out;

    cudaFuncSetAttribute(gemm_k, cudaFuncAttributeMaxDynamicSharedMemorySize, GEMM_SMEM);
    cudaFuncSetAttribute(flash_attn_kernel, cudaFuncAttributeMaxDynamicSharedMemorySize, FLASH_SMEM);

    split_src<<<(BSROWS * DD / 4) / 256, 256>>>(x);
    dim3 wgrid(32, 32);
    wsplit<<<wgrid, 256>>>(Wq, 0);
    wsplit<<<wgrid, 256>>>(Wk, 1);
    wsplit<<<wgrid, 256>>>(Wv, 2);
    wsplit<<<wgrid, 256>>>(Wo, 3);

    dim3 qkvgrid(BSROWS / 128, DD / 128, 3);    // (64, 8, 3)
    gemm_k<<<qkvgrid, 256, GEMM_SMEM>>>(bq, bk, bv, nullptr, -1);

    dim3 fgrid(SS / 64, BB * HH);               // (32, 64)
    flash_attn_kernel<<<fgrid, 128, FLASH_SMEM>>>(pm);

    dim3 ogrid(BSROWS / 128, DD / 128, 1);
    gemm_k<<<ogrid, 256, GEMM_SMEM>>>(bo, nullptr, nullptr, out, 3);
}

// round 5
// speedup vs baseline: 2.2507x; 1.0066x over previous
#include <cuda_runtime.h>
#include <cuda_bf16.h>
#include <cstdint>

// Problem constants
#define BB 4
#define SS 2048
#define DD 1024
#define HH 16
#define DHH 64
#define BSROWS (BB * SS)          // 8192

typedef __nv_bfloat16 bf16;

// ---------------------------------------------------------------------------
// Device-global scratch (allocation-free). All pre-split bf16 hi/mid pairs.
// ---------------------------------------------------------------------------
__device__ bf16 g_xh[(size_t)BSROWS * DD], g_xm[(size_t)BSROWS * DD];
__device__ bf16 g_qh[(size_t)BSROWS * DD], g_qm[(size_t)BSROWS * DD];
__device__ bf16 g_kh[(size_t)BSROWS * DD], g_km[(size_t)BSROWS * DD];
__device__ bf16 g_vh[(size_t)BSROWS * DD], g_vm[(size_t)BSROWS * DD];
__device__ bf16 g_ah[(size_t)BSROWS * DD], g_am[(size_t)BSROWS * DD];
__device__ bf16 g_wth[4 * (size_t)DD * DD], g_wtm[4 * (size_t)DD * DD];  // W^T [n][k]

#define LOG2E 1.4426950408889634f

// ---------------------------------------------------------------------------
// Helpers
// ---------------------------------------------------------------------------
__device__ __forceinline__ void mma_bf16(float* c, const unsigned* a, const unsigned* b) {
    asm volatile(
        "mma.sync.aligned.m16n8k16.row.col.f32.bf16.bf16.f32 "
        "{%0,%1,%2,%3}, {%4,%5,%6,%7}, {%8,%9}, {%0,%1,%2,%3};\n"
        : "+f"(c[0]), "+f"(c[1]), "+f"(c[2]), "+f"(c[3])
        : "r"(a[0]), "r"(a[1]), "r"(a[2]), "r"(a[3]),
          "r"(b[0]), "r"(b[1]));
}

__device__ __forceinline__ void ldm_x4(unsigned* r, uint32_t addr) {
    asm volatile("ldmatrix.sync.aligned.m8n8.x4.shared.b16 {%0,%1,%2,%3}, [%4];"
        : "=r"(r[0]), "=r"(r[1]), "=r"(r[2]), "=r"(r[3]) : "r"(addr));
}
__device__ __forceinline__ void ldm_x4t(unsigned* r, uint32_t addr) {
    asm volatile("ldmatrix.sync.aligned.m8n8.x4.trans.shared.b16 {%0,%1,%2,%3}, [%4];"
        : "=r"(r[0]), "=r"(r[1]), "=r"(r[2]), "=r"(r[3]) : "r"(addr));
}

__device__ __forceinline__ unsigned pack2(bf16 lo, bf16 hi) {
    unsigned l = __bfloat16_as_ushort(lo), h = __bfloat16_as_ushort(hi);
    return l | (h << 16);
}

__device__ __forceinline__ void bsplit(float x, bf16& h, bf16& m) {
    h = __float2bfloat16_rn(x);
    m = __float2bfloat16_rn(x - __bfloat162float(h));
}

__device__ __forceinline__ unsigned packHM(float x, float y, unsigned& mp) {
    bf16 hx, mx, hy, my;
    bsplit(x, hx, mx);
    bsplit(y, hy, my);
    mp = pack2(mx, my);
    return pack2(hx, hy);
}

__device__ __forceinline__ void cpa16(void* s, const void* g) {
    unsigned sa = (unsigned)__cvta_generic_to_shared(s);
    asm volatile("cp.async.cg.shared.global [%0], [%1], 16;\n" :: "r"(sa), "l"(g));
}
__device__ __forceinline__ void cpa_commit() {
    asm volatile("cp.async.commit_group;\n");
}
template <int N>
__device__ __forceinline__ void cpa_wait() {
    asm volatile("cp.async.wait_group %0;\n" :: "n"(N));
}

__device__ __forceinline__ uint32_t smem_u32(const void* p) {
    return (uint32_t)__cvta_generic_to_shared(p);
}

// ---------------------------------------------------------------------------
// Prep: split x (fp32 -> bf16 hi/mid)
// ---------------------------------------------------------------------------
__global__ __launch_bounds__(256)
void split_src(const float* __restrict__ x)
{
    int i = blockIdx.x * 256 + threadIdx.x;            // over float4s: 2M
    float4 v = reinterpret_cast<const float4*>(x)[i];
    bf16 h0, m0, h1, m1, h2, m2, h3, m3;
    bsplit(v.x, h0, m0); bsplit(v.y, h1, m1);
    bsplit(v.z, h2, m2); bsplit(v.w, h3, m3);
    uint2 uh, um;
    uh.x = pack2(h0, h1); uh.y = pack2(h2, h3);
    um.x = pack2(m0, m1); um.y = pack2(m2, m3);
    reinterpret_cast<uint2*>(g_xh)[i] = uh;
    reinterpret_cast<uint2*>(g_xm)[i] = um;
}

// ---------------------------------------------------------------------------
// Prep: transpose + split W [k][n] fp32 -> g_wt{h,m}[widx] as [n][k] bf16
// ---------------------------------------------------------------------------
__global__ __launch_bounds__(256)
void wsplit(const float* __restrict__ W, int widx)
{
    __shared__ float t[32][33];
    const int kb = blockIdx.x * 32, nb = blockIdx.y * 32;
    const int r = threadIdx.x >> 3, c4 = (threadIdx.x & 7) * 4;
    float4 v = *reinterpret_cast<const float4*>(W + (size_t)(kb + r) * DD + nb + c4);
    t[r][c4 + 0] = v.x; t[r][c4 + 1] = v.y; t[r][c4 + 2] = v.z; t[r][c4 + 3] = v.w;
    __syncthreads();
    bf16* oh = g_wth + (size_t)widx * DD * DD;
    bf16* om = g_wtm + (size_t)widx * DD * DD;
    bf16 h[4], m[4];
    #pragma unroll
    for (int j = 0; j < 4; j++) bsplit(t[c4 + j][r], h[j], m[j]);
    uint2 uh, um;
    uh.x = pack2(h[0], h[1]); uh.y = pack2(h[2], h[3]);
    um.x = pack2(m[0], m[1]); um.y = pack2(m[2], m[3]);
    size_t o = (size_t)(nb + r) * DD + kb + c4;
    *reinterpret_cast<uint2*>(oh + o) = uh;
    *reinterpret_cast<uint2*>(om + o) = um;
}

// ---------------------------------------------------------------------------
// GEMM (3xBF16, m16n8k16 + ldmatrix): C = A * W^T' + bias, M=8192, N=K=1024
// CTA tile 128x128, kstep 32, 256 threads (8 warps: 4 M x 2 N), cp.async dbuf.
// mode -1: md=blockIdx.z (QKV, A=g_x, out bf16 split to g_{q,k,v}, q scaled 1/8)
// mode  3: A=g_a (attended), out fp32 to outF
// ---------------------------------------------------------------------------
#define KS 32
#define AST 40
#define SLAB (2 * 128 * AST)                 // halves per (dbuf) array
#define GEMM_SMEM (4 * SLAB * 2)             // 81920 bytes
#define GMOFF (SLAB * 2)                     // hi->mid byte offset

__global__ __launch_bounds__(256, 2)
void gemm_k(const float* __restrict__ b0, const float* __restrict__ b1,
            const float* __restrict__ b2, float* __restrict__ outF, int mode)
{
    const int md = (mode < 0) ? (int)blockIdx.z : mode;
    const bf16* Ah = (md < 3) ? g_xh : g_ah;
    const bf16* Am = (md < 3) ? g_xm : g_am;
    const bf16* Wh = g_wth + (size_t)md * DD * DD;
    const bf16* Wm = g_wtm + (size_t)md * DD * DD;
    const float* bias = (md == 1) ? b1 : (md == 2) ? b2 : b0;
    const float scale = (md == 0) ? 0.125f : 1.0f;
    bf16* OH = (md == 0) ? g_qh : (md == 1) ? g_kh : g_vh;
    bf16* OM = (md == 0) ? g_qm : (md == 1) ? g_km : g_vm;

    extern __shared__ bf16 sm[];
    bf16* sAh = sm;
    bf16* sAm = sm + SLAB;
    bf16* sBh = sm + 2 * SLAB;
    bf16* sBm = sm + 3 * SLAB;
    const uint32_t uAh = smem_u32(sAh);
    const uint32_t uBh = smem_u32(sBh);

    const int tid  = threadIdx.x;
    const int lane = tid & 31;
    const int warp = tid >> 5;
    const int wm = warp & 3, wn = warp >> 2;
    const int cm = blockIdx.x * 128, cn = blockIdx.y * 128;
    const int rq = lane >> 2, cq = lane & 3;

    // ldmatrix lane->row mappings
    const int a_r = lane & 15, a_k = (lane >> 4) * 8;               // A x4
    const int b_n = ((lane >> 3) & 1) * 8 + (lane & 7);             // B x4 (pair of n-tiles)
    const int b_k = (lane >> 4) * 8;

    // issue stage kt into buffer buf
    auto issue = [&](int kt, int buf) {
        const int k0 = kt * KS;
        #pragma unroll
        for (int i = 0; i < 2; i++) {
            int idx = i * 256 + tid;
            int r = idx >> 2, c8 = (idx & 3) * 8;
            size_t ga = (size_t)(cm + r) * DD + k0 + c8;
            size_t gb = (size_t)(cn + r) * DD + k0 + c8;
            int so = buf * 128 * AST + r * AST + c8;
            cpa16(&sAh[so], Ah + ga);
            cpa16(&sAm[so], Am + ga);
            cpa16(&sBh[so], Wh + gb);
            cpa16(&sBm[so], Wm + gb);
        }
        cpa_commit();
    };

    float acc[2][8][4];
    #pragma unroll
    for (int mt = 0; mt < 2; mt++)
        #pragma unroll
        for (int nt = 0; nt < 8; nt++)
            #pragma unroll
            for (int j = 0; j < 4; j++) acc[mt][nt][j] = 0.f;

    const int NK = DD / KS;  // 32
    issue(0, 0);

    for (int kt = 0; kt < NK; ++kt) {
        int cur = kt & 1;
        if (kt + 1 < NK) { issue(kt + 1, cur ^ 1); cpa_wait<1>(); }
        else             { cpa_wait<0>(); }
        __syncthreads();

        const uint32_t bufOff = (uint32_t)(cur * 128 * AST * 2);
        #pragma unroll
        for (int ch = 0; ch < 2; ++ch) {
            const int kc = ch * 16;
            unsigned ah[2][4], am[2][4];
            #pragma unroll
            for (int mt = 0; mt < 2; mt++) {
                uint32_t ad = uAh + bufOff +
                    (uint32_t)(((wm * 32 + mt * 16 + a_r) * AST + kc + a_k) * 2);
                ldm_x4(ah[mt], ad);
                ldm_x4(am[mt], ad + GMOFF);
            }
            #pragma unroll
            for (int ntp = 0; ntp < 4; ntp++) {
                uint32_t bd = uBh + bufOff +
                    (uint32_t)(((wn * 64 + ntp * 16 + b_n) * AST + kc + b_k) * 2);
                unsigned kbh[4], kbm[4];
                ldm_x4(kbh, bd);
                ldm_x4(kbm, bd + GMOFF);
                unsigned bh0[2] = {kbh[0], kbh[2]}, bh1[2] = {kbh[1], kbh[3]};
                unsigned bm0[2] = {kbm[0], kbm[2]}, bm1[2] = {kbm[1], kbm[3]};
                #pragma unroll
                for (int mt = 0; mt < 2; mt++) {
                    mma_bf16(acc[mt][2 * ntp],     ah[mt], bh0);
                    mma_bf16(acc[mt][2 * ntp],     am[mt], bh0);
                    mma_bf16(acc[mt][2 * ntp],     ah[mt], bm0);
                    mma_bf16(acc[mt][2 * ntp + 1], ah[mt], bh1);
                    mma_bf16(acc[mt][2 * ntp + 1], am[mt], bh1);
                    mma_bf16(acc[mt][2 * ntp + 1], ah[mt], bm1);
                }
            }
        }
        __syncthreads();
    }

    // epilogue
    #pragma unroll
    for (int mt = 0; mt < 2; mt++) {
        int r = cm + wm * 32 + mt * 16 + rq;
        #pragma unroll
        for (int nt = 0; nt < 8; nt++) {
            int c = cn + wn * 64 + nt * 8 + cq * 2;
            float bb0 = bias[c], bb1 = bias[c + 1];
            float v0 = (acc[mt][nt][0] + bb0) * scale;
            float v1 = (acc[mt][nt][1] + bb1) * scale;
            float v2 = (acc[mt][nt][2] + bb0) * scale;
            float v3 = (acc[mt][nt][3] + bb1) * scale;
            if (md == 3) {
                *reinterpret_cast<float2*>(outF + (size_t)r * DD + c) = make_float2(v0, v1);
                *reinterpret_cast<float2*>(outF + (size_t)(r + 8) * DD + c) = make_float2(v2, v3);
            } else {
                bf16 h0, m0, h1, m1;
                bsplit(v0, h0, m0); bsplit(v1, h1, m1);
                *reinterpret_cast<unsigned*>(OH + (size_t)r * DD + c) = pack2(h0, h1);
                *reinterpret_cast<unsigned*>(OM + (size_t)r * DD + c) = pack2(m0, m1);
                bsplit(v2, h0, m0); bsplit(v3, h1, m1);
                *reinterpret_cast<unsigned*>(OH + (size_t)(r + 8) * DD + c) = pack2(h0, h1);
                *reinterpret_cast<unsigned*>(OM + (size_t)(r + 8) * DD + c) = pack2(m0, m1);
            }
        }
    }
}

// ---------------------------------------------------------------------------
// Flash attention (causal + key padding), 3xBF16 m16n8k16 + ldmatrix.
// Grid: (S/64, B*H), 128 threads = 4 warps; warp w owns query rows [16w,16w+16).
// Q pre-scaled by 1/8 in GEMM epilogue. P stays in registers (FA2 layout trick).
// V fragments via ldmatrix.trans (replaces 512 scalar LDS per iteration).
// ---------------------------------------------------------------------------
#define FST 72                                // smem k-stride (halves)
#define FQ  (64 * FST)                        // 4608 halves per array
#define FMOFF (FQ * 2)                        // hi->mid byte offset
#define FLASH_SMEM (6 * FQ * 2 + 64 * 4)      // 55552 bytes

__global__ __launch_bounds__(128, 3)
void flash_attn_kernel(const int* __restrict__ pmask)
{
    extern __shared__ bf16 fsm[];
    bf16* QH = fsm;
    bf16* QM = fsm + FQ;
    bf16* KH = fsm + 2 * FQ;
    bf16* KM = fsm + 3 * FQ;
    bf16* VH = fsm + 4 * FQ;
    bf16* VM = fsm + 5 * FQ;
    int* Ms = reinterpret_cast<int*>(fsm + 6 * FQ);
    const uint32_t uQH = smem_u32(QH);
    const uint32_t uKH = smem_u32(KH);
    const uint32_t uVH = smem_u32(VH);

    const int tid = threadIdx.x, lane = tid & 31, warp = tid >> 5;
    const int qb = (int)(gridDim.x - 1) - (int)blockIdx.x;  // heavy blocks first
    const int bh = blockIdx.y;
    const int b = bh >> 4, h = bh & 15;
    const size_t head_off = ((size_t)b * SS) * DD + (size_t)h * DHH;

    const int rq = lane >> 2, cq = lane & 3;
    const int row0 = warp * 16 + rq;

    // ldmatrix lane->row mappings
    const int a_r = lane & 15, a_k = (lane >> 4) * 8;      // Q (A, x4)
    const int b_n = ((lane >> 3) & 1) * 8 + (lane & 7);    // K (B, x4 pair)
    const int b_k = (lane >> 4) * 8;
    const int v_k = ((lane >> 3) & 1) * 8 + (lane & 7);    // V (B^T via x4.trans)
    const int v_n = (lane >> 4) * 8;

    // Q tile [64 x 64] hi/mid via cp.async
    #pragma unroll
    for (int i = 0; i < 4; i++) {
        int idx = i * 128 + tid;
        int r = idx >> 3, c8 = (idx & 7) * 8;
        size_t g = head_off + (size_t)(qb * 64 + r) * DD + c8;
        cpa16(&QH[r * FST + c8], g_qh + g);
        cpa16(&QM[r * FST + c8], g_qm + g);
    }
    cpa_commit();

    float o[8][4];
    #pragma unroll
    for (int nt = 0; nt < 8; nt++)
        #pragma unroll
        for (int j = 0; j < 4; j++) o[nt][j] = 0.f;
    float m0 = -1e30f, m1 = -1e30f, l0 = 0.f, l1 = 0.f;

    for (int kb = 0; kb <= qb; ++kb) {
        __syncthreads();   // smem reuse from previous iteration
        #pragma unroll
        for (int i = 0; i < 4; i++) {
            int idx = i * 128 + tid;
            int r = idx >> 3, c8 = (idx & 7) * 8;
            size_t g = head_off + (size_t)(kb * 64 + r) * DD + c8;
            cpa16(&KH[r * FST + c8], g_kh + g);
            cpa16(&KM[r * FST + c8], g_km + g);
            cpa16(&VH[r * FST + c8], g_vh + g);
            cpa16(&VM[r * FST + c8], g_vm + g);
        }
        cpa_commit();
        if (tid < 64) Ms[tid] = pmask[b * SS + kb * 64 + tid];
        cpa_wait<0>();
        __syncthreads();

        // --- S = Q K^T (warp: 16 x 64), 3xBF16 via ldmatrix ---
        float sc[8][4];
        #pragma unroll
        for (int nt = 0; nt < 8; nt++)
            #pragma unroll
            for (int j = 0; j < 4; j++) sc[nt][j] = 0.f;

        #pragma unroll
        for (int ch = 0; ch < 4; ++ch) {
            const int kc = ch * 16;
            unsigned ah[4], am[4];
            uint32_t qd = uQH + (uint32_t)(((warp * 16 + a_r) * FST + kc + a_k) * 2);
            ldm_x4(ah, qd);
            ldm_x4(am, qd + FMOFF);
            #pragma unroll
            for (int ntp = 0; ntp < 4; ntp++) {
                uint32_t kd = uKH + (uint32_t)(((ntp * 16 + b_n) * FST + kc + b_k) * 2);
                unsigned kbh[4], kbm[4];
                ldm_x4(kbh, kd);
                ldm_x4(kbm, kd + FMOFF);
                unsigned bh0[2] = {kbh[0], kbh[2]}, bh1[2] = {kbh[1], kbh[3]};
                unsigned bm0[2] = {kbm[0], kbm[2]}, bm1[2] = {kbm[1], kbm[3]};
                mma_bf16(sc[2 * ntp],     ah, bh0);
                mma_bf16(sc[2 * ntp],     am, bh0);
                mma_bf16(sc[2 * ntp],     ah, bm0);
                mma_bf16(sc[2 * ntp + 1], ah, bh1);
                mma_bf16(sc[2 * ntp + 1], am, bh1);
                mma_bf16(sc[2 * ntp + 1], ah, bm1);
            }
        }

        // --- mask (Q already scaled; sentinel -1e30) ---
        const int gm0 = qb * 64 + row0, gm1 = gm0 + 8;
        #pragma unroll
        for (int nt = 0; nt < 8; nt++) {
            int nloc = nt * 8 + cq * 2;
            int gn = kb * 64 + nloc;
            #pragma unroll
            for (int j = 0; j < 2; j++) {
                bool pv = (Ms[nloc + j] != 0);
                sc[nt][j]     = (pv && (gn + j) <= gm0) ? sc[nt][j]     : -1e30f;
                sc[nt][2 + j] = (pv && (gn + j) <= gm1) ? sc[nt][2 + j] : -1e30f;
            }
        }

        // --- online softmax (p written back into sc) ---
        float mx0 = -1e30f, mx1 = -1e30f;
        #pragma unroll
        for (int nt = 0; nt < 8; nt++) {
            mx0 = fmaxf(mx0, fmaxf(sc[nt][0], sc[nt][1]));
            mx1 = fmaxf(mx1, fmaxf(sc[nt][2], sc[nt][3]));
        }
        mx0 = fmaxf(mx0, __shfl_xor_sync(0xffffffffu, mx0, 1));
        mx0 = fmaxf(mx0, __shfl_xor_sync(0xffffffffu, mx0, 2));
        mx1 = fmaxf(mx1, __shfl_xor_sync(0xffffffffu, mx1, 1));
        mx1 = fmaxf(mx1, __shfl_xor_sync(0xffffffffu, mx1, 2));

        float mn0 = fmaxf(m0, mx0), mn1 = fmaxf(m1, mx1);
        float al0 = exp2f((m0 - mn0) * LOG2E);
        float al1 = exp2f((m1 - mn1) * LOG2E);

        float s0 = 0.f, s1 = 0.f;
        #pragma unroll
        for (int nt = 0; nt < 8; nt++) {
            sc[nt][0] = exp2f((sc[nt][0] - mn0) * LOG2E);
            sc[nt][1] = exp2f((sc[nt][1] - mn0) * LOG2E);
            sc[nt][2] = exp2f((sc[nt][2] - mn1) * LOG2E);
            sc[nt][3] = exp2f((sc[nt][3] - mn1) * LOG2E);
            s0 += sc[nt][0] + sc[nt][1];
            s1 += sc[nt][2] + sc[nt][3];
        }
        s0 += __shfl_xor_sync(0xffffffffu, s0, 1);
        s0 += __shfl_xor_sync(0xffffffffu, s0, 2);
        s1 += __shfl_xor_sync(0xffffffffu, s1, 1);
        s1 += __shfl_xor_sync(0xffffffffu, s1, 2);

        l0 = l0 * al0 + s0;
        l1 = l1 * al1 + s1;
        m0 = mn0; m1 = mn1;

        #pragma unroll
        for (int nt = 0; nt < 8; nt++) {
            o[nt][0] *= al0; o[nt][1] *= al0;
            o[nt][2] *= al1; o[nt][3] *= al1;
        }

        // --- O += P V: A from S registers; V fragments via ldmatrix.trans ---
        #pragma unroll
        for (int ch = 0; ch < 4; ++ch) {
            const int kc = ch * 16;
            const int t0 = 2 * ch, t1 = 2 * ch + 1;
            unsigned ah[4], am[4];
            ah[0] = packHM(sc[t0][0], sc[t0][1], am[0]);
            ah[1] = packHM(sc[t0][2], sc[t0][3], am[1]);
            ah[2] = packHM(sc[t1][0], sc[t1][1], am[2]);
            ah[3] = packHM(sc[t1][2], sc[t1][3], am[3]);
            #pragma unroll
            for (int ntp = 0; ntp < 4; ntp++) {
                uint32_t vd = uVH + (uint32_t)(((kc + v_k) * FST + ntp * 16 + v_n) * 2);
                unsigned vbh[4], vbm[4];
                ldm_x4t(vbh, vd);
                ldm_x4t(vbm, vd + FMOFF);
                unsigned bh0[2] = {vbh[0], vbh[1]}, bh1[2] = {vbh[2], vbh[3]};
                unsigned bm0[2] = {vbm[0], vbm[1]}, bm1[2] = {vbm[2], vbm[3]};
                mma_bf16(o[2 * ntp],     ah, bh0);
                mma_bf16(o[2 * ntp],     am, bh0);
                mma_bf16(o[2 * ntp],     ah, bm0);
                mma_bf16(o[2 * ntp + 1], ah, bh1);
                mma_bf16(o[2 * ntp + 1], am, bh1);
                mma_bf16(o[2 * ntp + 1], ah, bm1);
            }
        }
    }

    // --- epilogue: normalize, split, store to g_a{h,m} [b, s, h, dh] ---
    float i0 = (l0 > 0.f) ? 1.f / l0 : 0.f;
    float i1 = (l1 > 0.f) ? 1.f / l1 : 0.f;
    size_t ob = head_off + (size_t)(qb * 64) * DD;
    #pragma unroll
    for (int nt = 0; nt < 8; nt++) {
        int c = nt * 8 + cq * 2;
        bf16 h0, mm0, h1, mm1;
        bsplit(o[nt][0] * i0, h0, mm0); bsplit(o[nt][1] * i0, h1, mm1);
        *reinterpret_cast<unsigned*>(g_ah + ob + (size_t)row0 * DD + c) = pack2(h0, h1);
        *reinterpret_cast<unsigned*>(g_am + ob + (size_t)row0 * DD + c) = pack2(mm0, mm1);
        bsplit(o[nt][2] * i1, h0, mm0); bsplit(o[nt][3] * i1, h1, mm1);
        *reinterpret_cast<unsigned*>(g_ah + ob + (size_t)(row0 + 8) * DD + c) = pack2(h0, h1);
        *reinterpret_cast<unsigned*>(g_am + ob + (size_t)(row0 + 8) * DD + c) = pack2(mm0, mm1);
    }
}

// ---------------------------------------------------------------------------
extern "C" void kernel_launch(void* const* d_in, const int* in_sizes, int n_in,
                              void* d_out, int out_size)
{
    (void)in_sizes; (void)n_in; (void)out_size;
    const float* x  = (const float*)d_in[0];
    const float* Wq = (const float*)d_in[1];
    const float* bq = (const float*)d_in[2];
    const float* Wk = (const float*)d_in[3];
    const float* bk = (const float*)d_in[4];
    const float* Wv = (const float*)d_in[5];
    const float* bv = (const float*)d_in[6];
    const float* Wo = (const float*)d_in[7];
    const float* bo = (const float*)d_in[8];
    const int*   pm = (const int*)d_in[9];
    float* out = (float*)d_out;

    cudaFuncSetAttribute(gemm_k, cudaFuncAttributeMaxDynamicSharedMemorySize, GEMM_SMEM);
    cudaFuncSetAttribute(flash_attn_kernel, cudaFuncAttributeMaxDynamicSharedMemorySize, FLASH_SMEM);

    split_src<<<(BSROWS * DD / 4) / 256, 256>>>(x);
    dim3 wgrid(32, 32);
    wsplit<<<wgrid, 256>>>(Wq, 0);
    wsplit<<<wgrid, 256>>>(Wk, 1);
    wsplit<<<wgrid, 256>>>(Wv, 2);
    wsplit<<<wgrid, 256>>>(Wo, 3);

    dim3 qkvgrid(BSROWS / 128, DD / 128, 3);    // (64, 8, 3)
    gemm_k<<<qkvgrid, 256, GEMM_SMEM>>>(bq, bk, bv, nullptr, -1);

    dim3 fgrid(SS / 64, BB * HH);               // (32, 64)
    flash_attn_kernel<<<fgrid, 128, FLASH_SMEM>>>(pm);

    dim3 ogrid(BSROWS / 128, DD / 128, 1);
    gemm_k<<<ogrid, 256, GEMM_SMEM>>>(bo, nullptr, nullptr, out, 3);
}

// round 6
// speedup vs baseline: 2.2648x; 1.0063x over previous
#include <cuda_runtime.h>
#include <cuda_bf16.h>
#include <cstdint>

// Problem constants
#define BB 4
#define SS 2048
#define DD 1024
#define HH 16
#define DHH 64
#define BSROWS (BB * SS)          // 8192

typedef __nv_bfloat16 bf16;

// ---------------------------------------------------------------------------
// Device-global scratch (allocation-free). All pre-split bf16 hi/mid pairs.
// ---------------------------------------------------------------------------
__device__ bf16 g_xh[(size_t)BSROWS * DD], g_xm[(size_t)BSROWS * DD];
__device__ bf16 g_qh[(size_t)BSROWS * DD], g_qm[(size_t)BSROWS * DD];
__device__ bf16 g_kh[(size_t)BSROWS * DD], g_km[(size_t)BSROWS * DD];
__device__ bf16 g_vh[(size_t)BSROWS * DD], g_vm[(size_t)BSROWS * DD];
__device__ bf16 g_ah[(size_t)BSROWS * DD], g_am[(size_t)BSROWS * DD];
__device__ bf16 g_wth[4 * (size_t)DD * DD], g_wtm[4 * (size_t)DD * DD];  // W^T [n][k]

#define LOG2E 1.4426950408889634f

// ---------------------------------------------------------------------------
// Helpers
// ---------------------------------------------------------------------------
__device__ __forceinline__ void mma_bf16(float* c, const unsigned* a, const unsigned* b) {
    asm volatile(
        "mma.sync.aligned.m16n8k16.row.col.f32.bf16.bf16.f32 "
        "{%0,%1,%2,%3}, {%4,%5,%6,%7}, {%8,%9}, {%0,%1,%2,%3};\n"
        : "+f"(c[0]), "+f"(c[1]), "+f"(c[2]), "+f"(c[3])
        : "r"(a[0]), "r"(a[1]), "r"(a[2]), "r"(a[3]),
          "r"(b[0]), "r"(b[1]));
}

__device__ __forceinline__ void ldm_x4(unsigned* r, uint32_t addr) {
    asm volatile("ldmatrix.sync.aligned.m8n8.x4.shared.b16 {%0,%1,%2,%3}, [%4];"
        : "=r"(r[0]), "=r"(r[1]), "=r"(r[2]), "=r"(r[3]) : "r"(addr));
}
__device__ __forceinline__ void ldm_x4t(unsigned* r, uint32_t addr) {
    asm volatile("ldmatrix.sync.aligned.m8n8.x4.trans.shared.b16 {%0,%1,%2,%3}, [%4];"
        : "=r"(r[0]), "=r"(r[1]), "=r"(r[2]), "=r"(r[3]) : "r"(addr));
}

__device__ __forceinline__ unsigned pack2(bf16 lo, bf16 hi) {
    unsigned l = __bfloat16_as_ushort(lo), h = __bfloat16_as_ushort(hi);
    return l | (h << 16);
}

__device__ __forceinline__ void bsplit(float x, bf16& h, bf16& m) {
    h = __float2bfloat16_rn(x);
    m = __float2bfloat16_rn(x - __bfloat162float(h));
}

__device__ __forceinline__ unsigned packHM(float x, float y, unsigned& mp) {
    bf16 hx, mx, hy, my;
    bsplit(x, hx, mx);
    bsplit(y, hy, my);
    mp = pack2(mx, my);
    return pack2(hx, hy);
}

__device__ __forceinline__ void cpa16(void* s, const void* g) {
    unsigned sa = (unsigned)__cvta_generic_to_shared(s);
    asm volatile("cp.async.cg.shared.global [%0], [%1], 16;\n" :: "r"(sa), "l"(g));
}
__device__ __forceinline__ void cpa4(void* s, const void* g) {
    unsigned sa = (unsigned)__cvta_generic_to_shared(s);
    asm volatile("cp.async.ca.shared.global [%0], [%1], 4;\n" :: "r"(sa), "l"(g));
}
__device__ __forceinline__ void cpa_commit() {
    asm volatile("cp.async.commit_group;\n");
}
template <int N>
__device__ __forceinline__ void cpa_wait() {
    asm volatile("cp.async.wait_group %0;\n" :: "n"(N));
}

__device__ __forceinline__ uint32_t smem_u32(const void* p) {
    return (uint32_t)__cvta_generic_to_shared(p);
}

// ---------------------------------------------------------------------------
// Prep: split x (fp32 -> bf16 hi/mid)
// ---------------------------------------------------------------------------
__global__ __launch_bounds__(256)
void split_src(const float* __restrict__ x)
{
    int i = blockIdx.x * 256 + threadIdx.x;            // over float4s: 2M
    float4 v = reinterpret_cast<const float4*>(x)[i];
    bf16 h0, m0, h1, m1, h2, m2, h3, m3;
    bsplit(v.x, h0, m0); bsplit(v.y, h1, m1);
    bsplit(v.z, h2, m2); bsplit(v.w, h3, m3);
    uint2 uh, um;
    uh.x = pack2(h0, h1); uh.y = pack2(h2, h3);
    um.x = pack2(m0, m1); um.y = pack2(m2, m3);
    reinterpret_cast<uint2*>(g_xh)[i] = uh;
    reinterpret_cast<uint2*>(g_xm)[i] = um;
}

// ---------------------------------------------------------------------------
// Prep: transpose + split all 4 W [k][n] fp32 -> g_wt{h,m}[z] as [n][k] bf16
// ---------------------------------------------------------------------------
__global__ __launch_bounds__(256)
void wsplit_all(const float* __restrict__ W0, const float* __restrict__ W1,
                const float* __restrict__ W2, const float* __restrict__ W3)
{
    const int widx = blockIdx.z;
    const float* W = (widx == 0) ? W0 : (widx == 1) ? W1 : (widx == 2) ? W2 : W3;
    __shared__ float t[32][33];
    const int kb = blockIdx.x * 32, nb = blockIdx.y * 32;
    const int r = threadIdx.x >> 3, c4 = (threadIdx.x & 7) * 4;
    float4 v = *reinterpret_cast<const float4*>(W + (size_t)(kb + r) * DD + nb + c4);
    t[r][c4 + 0] = v.x; t[r][c4 + 1] = v.y; t[r][c4 + 2] = v.z; t[r][c4 + 3] = v.w;
    __syncthreads();
    bf16* oh = g_wth + (size_t)widx * DD * DD;
    bf16* om = g_wtm + (size_t)widx * DD * DD;
    bf16 h[4], m[4];
    #pragma unroll
    for (int j = 0; j < 4; j++) bsplit(t[c4 + j][r], h[j], m[j]);
    uint2 uh, um;
    uh.x = pack2(h[0], h[1]); uh.y = pack2(h[2], h[3]);
    um.x = pack2(m[0], m[1]); um.y = pack2(m[2], m[3]);
    size_t o = (size_t)(nb + r) * DD + kb + c4;
    *reinterpret_cast<uint2*>(oh + o) = uh;
    *reinterpret_cast<uint2*>(om + o) = um;
}

// ---------------------------------------------------------------------------
// GEMM (3xBF16, m16n8k16 + ldmatrix): C = A * W^T' + bias, M=8192, N=K=1024
// CTA tile 128x128, kstep 32, 256 threads (8 warps: 4 M x 2 N), cp.async dbuf.
// mode -1: md=blockIdx.z (QKV, A=g_x, out bf16 split to g_{q,k,v}, q scaled 1/8)
// mode  3: A=g_a (attended), out fp32 to outF
// ---------------------------------------------------------------------------
#define KS 32
#define AST 40
#define SLAB (2 * 128 * AST)                 // halves per (dbuf) array
#define GEMM_SMEM (4 * SLAB * 2)             // 81920 bytes
#define GMOFF (SLAB * 2)                     // hi->mid byte offset

__global__ __launch_bounds__(256, 2)
void gemm_k(const float* __restrict__ b0, const float* __restrict__ b1,
            const float* __restrict__ b2, float* __restrict__ outF, int mode)
{
    const int md = (mode < 0) ? (int)blockIdx.z : mode;
    const bf16* Ah = (md < 3) ? g_xh : g_ah;
    const bf16* Am = (md < 3) ? g_xm : g_am;
    const bf16* Wh = g_wth + (size_t)md * DD * DD;
    const bf16* Wm = g_wtm + (size_t)md * DD * DD;
    const float* bias = (md == 1) ? b1 : (md == 2) ? b2 : b0;
    const float scale = (md == 0) ? 0.125f : 1.0f;
    bf16* OH = (md == 0) ? g_qh : (md == 1) ? g_kh : g_vh;
    bf16* OM = (md == 0) ? g_qm : (md == 1) ? g_km : g_vm;

    extern __shared__ bf16 sm[];
    bf16* sAh = sm;
    bf16* sAm = sm + SLAB;
    bf16* sBh = sm + 2 * SLAB;
    bf16* sBm = sm + 3 * SLAB;
    const uint32_t uAh = smem_u32(sAh);
    const uint32_t uBh = smem_u32(sBh);

    const int tid  = threadIdx.x;
    const int lane = tid & 31;
    const int warp = tid >> 5;
    const int wm = warp & 3, wn = warp >> 2;
    const int cm = blockIdx.x * 128, cn = blockIdx.y * 128;
    const int rq = lane >> 2, cq = lane & 3;

    // ldmatrix lane->row mappings
    const int a_r = lane & 15, a_k = (lane >> 4) * 8;               // A x4
    const int b_n = ((lane >> 3) & 1) * 8 + (lane & 7);             // B x4 (pair of n-tiles)
    const int b_k = (lane >> 4) * 8;

    // issue stage kt into buffer buf
    auto issue = [&](int kt, int buf) {
        const int k0 = kt * KS;
        #pragma unroll
        for (int i = 0; i < 2; i++) {
            int idx = i * 256 + tid;
            int r = idx >> 2, c8 = (idx & 3) * 8;
            size_t ga = (size_t)(cm + r) * DD + k0 + c8;
            size_t gb = (size_t)(cn + r) * DD + k0 + c8;
            int so = buf * 128 * AST + r * AST + c8;
            cpa16(&sAh[so], Ah + ga);
            cpa16(&sAm[so], Am + ga);
            cpa16(&sBh[so], Wh + gb);
            cpa16(&sBm[so], Wm + gb);
        }
        cpa_commit();
    };

    float acc[2][8][4];
    #pragma unroll
    for (int mt = 0; mt < 2; mt++)
        #pragma unroll
        for (int nt = 0; nt < 8; nt++)
            #pragma unroll
            for (int j = 0; j < 4; j++) acc[mt][nt][j] = 0.f;

    const int NK = DD / KS;  // 32
    issue(0, 0);

    for (int kt = 0; kt < NK; ++kt) {
        int cur = kt & 1;
        if (kt + 1 < NK) { issue(kt + 1, cur ^ 1); cpa_wait<1>(); }
        else             { cpa_wait<0>(); }
        __syncthreads();

        const uint32_t bufOff = (uint32_t)(cur * 128 * AST * 2);
        #pragma unroll
        for (int ch = 0; ch < 2; ++ch) {
            const int kc = ch * 16;
            unsigned ah[2][4], am[2][4];
            #pragma unroll
            for (int mt = 0; mt < 2; mt++) {
                uint32_t ad = uAh + bufOff +
                    (uint32_t)(((wm * 32 + mt * 16 + a_r) * AST + kc + a_k) * 2);
                ldm_x4(ah[mt], ad);
                ldm_x4(am[mt], ad + GMOFF);
            }
            #pragma unroll
            for (int ntp = 0; ntp < 4; ntp++) {
                uint32_t bd = uBh + bufOff +
                    (uint32_t)(((wn * 64 + ntp * 16 + b_n) * AST + kc + b_k) * 2);
                unsigned kbh[4], kbm[4];
                ldm_x4(kbh, bd);
                ldm_x4(kbm, bd + GMOFF);
                unsigned bh0[2] = {kbh[0], kbh[2]}, bh1[2] = {kbh[1], kbh[3]};
                unsigned bm0[2] = {kbm[0], kbm[2]}, bm1[2] = {kbm[1], kbm[3]};
                #pragma unroll
                for (int mt = 0; mt < 2; mt++) {
                    mma_bf16(acc[mt][2 * ntp],     ah[mt], bh0);
                    mma_bf16(acc[mt][2 * ntp],     am[mt], bh0);
                    mma_bf16(acc[mt][2 * ntp],     ah[mt], bm0);
                    mma_bf16(acc[mt][2 * ntp + 1], ah[mt], bh1);
                    mma_bf16(acc[mt][2 * ntp + 1], am[mt], bh1);
                    mma_bf16(acc[mt][2 * ntp + 1], ah[mt], bm1);
                }
            }
        }
        __syncthreads();
    }

    // epilogue
    #pragma unroll
    for (int mt = 0; mt < 2; mt++) {
        int r = cm + wm * 32 + mt * 16 + rq;
        #pragma unroll
        for (int nt = 0; nt < 8; nt++) {
            int c = cn + wn * 64 + nt * 8 + cq * 2;
            float bb0 = bias[c], bb1 = bias[c + 1];
            float v0 = (acc[mt][nt][0] + bb0) * scale;
            float v1 = (acc[mt][nt][1] + bb1) * scale;
            float v2 = (acc[mt][nt][2] + bb0) * scale;
            float v3 = (acc[mt][nt][3] + bb1) * scale;
            if (md == 3) {
                *reinterpret_cast<float2*>(outF + (size_t)r * DD + c) = make_float2(v0, v1);
                *reinterpret_cast<float2*>(outF + (size_t)(r + 8) * DD + c) = make_float2(v2, v3);
            } else {
                bf16 h0, m0, h1, m1;
                bsplit(v0, h0, m0); bsplit(v1, h1, m1);
                *reinterpret_cast<unsigned*>(OH + (size_t)r * DD + c) = pack2(h0, h1);
                *reinterpret_cast<unsigned*>(OM + (size_t)r * DD + c) = pack2(m0, m1);
                bsplit(v2, h0, m0); bsplit(v3, h1, m1);
                *reinterpret_cast<unsigned*>(OH + (size_t)(r + 8) * DD + c) = pack2(h0, h1);
                *reinterpret_cast<unsigned*>(OM + (size_t)(r + 8) * DD + c) = pack2(m0, m1);
            }
        }
    }
}

// ---------------------------------------------------------------------------
// Flash attention (causal + key padding), 3xBF16 m16n8k16 + ldmatrix.
// Pipelined: K double-buffered (+mask), V single-buffered with deferred issue.
// Grid: (S/64, B*H), 128 threads = 4 warps; warp w owns query rows [16w,16w+16).
// smem arrays (FQ halves each): QH QM | KH0 KM0 KH1 KM1 | VH VM, then Ms[2][64].
// ---------------------------------------------------------------------------
#define FST 72                                // smem k-stride (halves)
#define FQ  (64 * FST)                        // 4608 halves per array
#define FMOFF (FQ * 2)                        // hi->mid byte offset (adjacent arrays)
#define FLASH_SMEM (8 * FQ * 2 + 2 * 64 * 4)  // 74240 bytes

__global__ __launch_bounds__(128, 3)
void flash_attn_kernel(const int* __restrict__ pmask)
{
    extern __shared__ bf16 fsm[];
    bf16* QH = fsm;                                    // +QM at FQ
    int* Ms0 = reinterpret_cast<int*>(fsm + 8 * FQ);   // Ms[2][64]
    const uint32_t uQH = smem_u32(QH);

    const int tid = threadIdx.x, lane = tid & 31, warp = tid >> 5;
    const int qb = (int)(gridDim.x - 1) - (int)blockIdx.x;  // heavy blocks first
    const int bh = blockIdx.y;
    const int b = bh >> 4, h = bh & 15;
    const size_t head_off = ((size_t)b * SS) * DD + (size_t)h * DHH;

    const int rq = lane >> 2, cq = lane & 3;
    const int row0 = warp * 16 + rq;

    // ldmatrix lane->row mappings
    const int a_r = lane & 15, a_k = (lane >> 4) * 8;      // Q (A, x4)
    const int b_n = ((lane >> 3) & 1) * 8 + (lane & 7);    // K (B, x4 pair)
    const int b_k = (lane >> 4) * 8;
    const int v_k = ((lane >> 3) & 1) * 8 + (lane & 7);    // V (B^T via x4.trans)
    const int v_n = (lane >> 4) * 8;

    // K(kb) + mask(kb) into K buffer (kb&1); own commit group
    auto issueK = [&](int kb) {
        bf16* KH = fsm + (2 + 2 * (kb & 1)) * FQ;
        bf16* KM = KH + FQ;
        #pragma unroll
        for (int i = 0; i < 4; i++) {
            int idx = i * 128 + tid;
            int r = idx >> 3, c8 = (idx & 7) * 8;
            size_t g = head_off + (size_t)(kb * 64 + r) * DD + c8;
            cpa16(&KH[r * FST + c8], g_kh + g);
            cpa16(&KM[r * FST + c8], g_km + g);
        }
        if (tid < 64) cpa4(&Ms0[(kb & 1) * 64 + tid], pmask + b * SS + kb * 64 + tid);
        cpa_commit();
    };
    // V(kb) into the single V buffer; own commit group
    auto issueV = [&](int kb) {
        bf16* VH = fsm + 6 * FQ;
        bf16* VM = VH + FQ;
        #pragma unroll
        for (int i = 0; i < 4; i++) {
            int idx = i * 128 + tid;
            int r = idx >> 3, c8 = (idx & 7) * 8;
            size_t g = head_off + (size_t)(kb * 64 + r) * DD + c8;
            cpa16(&VH[r * FST + c8], g_vh + g);
            cpa16(&VM[r * FST + c8], g_vm + g);
        }
        cpa_commit();
    };

    // Preload: Q (group), K0+mask0 (group), V0 (group)
    #pragma unroll
    for (int i = 0; i < 4; i++) {
        int idx = i * 128 + tid;
        int r = idx >> 3, c8 = (idx & 7) * 8;
        size_t g = head_off + (size_t)(qb * 64 + r) * DD + c8;
        cpa16(&QH[r * FST + c8], g_qh + g);
        cpa16(&QH[FQ + r * FST + c8], g_qm + g);
    }
    cpa_commit();
    issueK(0);
    issueV(0);

    float o[8][4];
    #pragma unroll
    for (int nt = 0; nt < 8; nt++)
        #pragma unroll
        for (int j = 0; j < 4; j++) o[nt][j] = 0.f;
    float m0 = -1e30f, m1 = -1e30f, l0 = 0.f, l1 = 0.f;

    for (int kb = 0; kb <= qb; ++kb) {
        // K(kb) [+Q on first iter] ready; V(kb) may still be in flight
        cpa_wait<1>();
        __syncthreads();

        const uint32_t uKH = smem_u32(fsm + (2 + 2 * (kb & 1)) * FQ);
        const int* Ms = Ms0 + (kb & 1) * 64;

        // --- S = Q K^T (warp: 16 x 64), 3xBF16 via ldmatrix ---
        float sc[8][4];
        #pragma unroll
        for (int nt = 0; nt < 8; nt++)
            #pragma unroll
            for (int j = 0; j < 4; j++) sc[nt][j] = 0.f;

        #pragma unroll
        for (int ch = 0; ch < 4; ++ch) {
            const int kc = ch * 16;
            unsigned ah[4], am[4];
            uint32_t qd = uQH + (uint32_t)(((warp * 16 + a_r) * FST + kc + a_k) * 2);
            ldm_x4(ah, qd);
            ldm_x4(am, qd + FMOFF);
            #pragma unroll
            for (int ntp = 0; ntp < 4; ntp++) {
                uint32_t kd = uKH + (uint32_t)(((ntp * 16 + b_n) * FST + kc + b_k) * 2);
                unsigned kbh[4], kbm[4];
                ldm_x4(kbh, kd);
                ldm_x4(kbm, kd + FMOFF);
                unsigned bh0[2] = {kbh[0], kbh[2]}, bh1[2] = {kbh[1], kbh[3]};
                unsigned bm0[2] = {kbm[0], kbm[2]}, bm1[2] = {kbm[1], kbm[3]};
                mma_bf16(sc[2 * ntp],     ah, bh0);
                mma_bf16(sc[2 * ntp],     am, bh0);
                mma_bf16(sc[2 * ntp],     ah, bm0);
                mma_bf16(sc[2 * ntp + 1], ah, bh1);
                mma_bf16(sc[2 * ntp + 1], am, bh1);
                mma_bf16(sc[2 * ntp + 1], ah, bm1);
            }
        }

        // Prefetch K(kb+1) into the other K buffer (overlaps softmax + PV + next QK)
        if (kb < qb) issueK(kb + 1);

        // --- mask (Q already scaled; sentinel -1e30) ---
        const int gm0 = qb * 64 + row0, gm1 = gm0 + 8;
        #pragma unroll
        for (int nt = 0; nt < 8; nt++) {
            int nloc = nt * 8 + cq * 2;
            int gn = kb * 64 + nloc;
            #pragma unroll
            for (int j = 0; j < 2; j++) {
                bool pv = (Ms[nloc + j] != 0);
                sc[nt][j]     = (pv && (gn + j) <= gm0) ? sc[nt][j]     : -1e30f;
                sc[nt][2 + j] = (pv && (gn + j) <= gm1) ? sc[nt][2 + j] : -1e30f;
            }
        }

        // --- online softmax (p written back into sc) ---
        float mx0 = -1e30f, mx1 = -1e30f;
        #pragma unroll
        for (int nt = 0; nt < 8; nt++) {
            mx0 = fmaxf(mx0, fmaxf(sc[nt][0], sc[nt][1]));
            mx1 = fmaxf(mx1, fmaxf(sc[nt][2], sc[nt][3]));
        }
        mx0 = fmaxf(mx0, __shfl_xor_sync(0xffffffffu, mx0, 1));
        mx0 = fmaxf(mx0, __shfl_xor_sync(0xffffffffu, mx0, 2));
        mx1 = fmaxf(mx1, __shfl_xor_sync(0xffffffffu, mx1, 1));
        mx1 = fmaxf(mx1, __shfl_xor_sync(0xffffffffu, mx1, 2));

        float mn0 = fmaxf(m0, mx0), mn1 = fmaxf(m1, mx1);
        float al0 = exp2f((m0 - mn0) * LOG2E);
        float al1 = exp2f((m1 - mn1) * LOG2E);

        float s0 = 0.f, s1 = 0.f;
        #pragma unroll
        for (int nt = 0; nt < 8; nt++) {
            sc[nt][0] = exp2f((sc[nt][0] - mn0) * LOG2E);
            sc[nt][1] = exp2f((sc[nt][1] - mn0) * LOG2E);
            sc[nt][2] = exp2f((sc[nt][2] - mn1) * LOG2E);
            sc[nt][3] = exp2f((sc[nt][3] - mn1) * LOG2E);
            s0 += sc[nt][0] + sc[nt][1];
            s1 += sc[nt][2] + sc[nt][3];
        }
        s0 += __shfl_xor_sync(0xffffffffu, s0, 1);
        s0 += __shfl_xor_sync(0xffffffffu, s0, 2);
        s1 += __shfl_xor_sync(0xffffffffu, s1, 1);
        s1 += __shfl_xor_sync(0xffffffffu, s1, 2);

        l0 = l0 * al0 + s0;
        l1 = l1 * al1 + s1;
        m0 = mn0; m1 = mn1;

        #pragma unroll
        for (int nt = 0; nt < 8; nt++) {
            o[nt][0] *= al0; o[nt][1] *= al0;
            o[nt][2] *= al1; o[nt][3] *= al1;
        }

        // V(kb) ready (allow K(kb+1) to stay in flight; none pending on last iter)
        if (kb < qb) cpa_wait<1>();
        else         cpa_wait<0>();
        __syncthreads();

        // --- O += P V: A from S registers; V fragments via ldmatrix.trans ---
        const uint32_t uVH = smem_u32(fsm + 6 * FQ);
        #pragma unroll
        for (int ch = 0; ch < 4; ++ch) {
            const int kc = ch * 16;
            const int t0 = 2 * ch, t1 = 2 * ch + 1;
            unsigned ah[4], am[4];
            ah[0] = packHM(sc[t0][0], sc[t0][1], am[0]);
            ah[1] = packHM(sc[t0][2], sc[t0][3], am[1]);
            ah[2] = packHM(sc[t1][0], sc[t1][1], am[2]);
            ah[3] = packHM(sc[t1][2], sc[t1][3], am[3]);
            #pragma unroll
            for (int ntp = 0; ntp < 4; ntp++) {
                uint32_t vd = uVH + (uint32_t)(((kc + v_k) * FST + ntp * 16 + v_n) * 2);
                unsigned vbh[4], vbm[4];
                ldm_x4t(vbh, vd);
                ldm_x4t(vbm, vd + FMOFF);
                unsigned bh0[2] = {vbh[0], vbh[1]}, bh1[2] = {vbh[2], vbh[3]};
                unsigned bm0[2] = {vbm[0], vbm[1]}, bm1[2] = {vbm[2], vbm[3]};
                mma_bf16(o[2 * ntp],     ah, bh0);
                mma_bf16(o[2 * ntp],     am, bh0);
                mma_bf16(o[2 * ntp],     ah, bm0);
                mma_bf16(o[2 * ntp + 1], ah, bh1);
                mma_bf16(o[2 * ntp + 1], am, bh1);
                mma_bf16(o[2 * ntp + 1], ah, bm1);
            }
        }

        // all warps done reading V before refilling it
        __syncthreads();
        if (kb < qb) issueV(kb + 1);
    }

    // --- epilogue: normalize, split, store to g_a{h,m} [b, s, h, dh] ---
    float i0 = (l0 > 0.f) ? 1.f / l0 : 0.f;
    float i1 = (l1 > 0.f) ? 1.f / l1 : 0.f;
    size_t ob = head_off + (size_t)(qb * 64) * DD;
    #pragma unroll
    for (int nt = 0; nt < 8; nt++) {
        int c = nt * 8 + cq * 2;
        bf16 h0, mm0, h1, mm1;
        bsplit(o[nt][0] * i0, h0, mm0); bsplit(o[nt][1] * i0, h1, mm1);
        *reinterpret_cast<unsigned*>(g_ah + ob + (size_t)row0 * DD + c) = pack2(h0, h1);
        *reinterpret_cast<unsigned*>(g_am + ob + (size_t)row0 * DD + c) = pack2(mm0, mm1);
        bsplit(o[nt][2] * i1, h0, mm0); bsplit(o[nt][3] * i1, h1, mm1);
        *reinterpret_cast<unsigned*>(g_ah + ob + (size_t)(row0 + 8) * DD + c) = pack2(h0, h1);
        *reinterpret_cast<unsigned*>(g_am + ob + (size_t)(row0 + 8) * DD + c) = pack2(mm0, mm1);
    }
}

// ---------------------------------------------------------------------------
extern "C" void kernel_launch(void* const* d_in, const int* in_sizes, int n_in,
                              void* d_out, int out_size)
{
    (void)in_sizes; (void)n_in; (void)out_size;
    const float* x  = (const float*)d_in[0];
    const float* Wq = (const float*)d_in[1];
    const float* bq = (const float*)d_in[2];
    const float* Wk = (const float*)d_in[3];
    const float* bk = (const float*)d_in[4];
    const float* Wv = (const float*)d_in[5];
    const float* bv = (const float*)d_in[6];
    const float* Wo = (const float*)d_in[7];
    const float* bo = (const float*)d_in[8];
    const int*   pm = (const int*)d_in[9];
    float* out = (float*)d_out;

    cudaFuncSetAttribute(gemm_k, cudaFuncAttributeMaxDynamicSharedMemorySize, GEMM_SMEM);
    cudaFuncSetAttribute(flash_attn_kernel, cudaFuncAttributeMaxDynamicSharedMemorySize, FLASH_SMEM);

    split_src<<<(BSROWS * DD / 4) / 256, 256>>>(x);
    dim3 wgrid(32, 32, 4);
    wsplit_all<<<wgrid, 256>>>(Wq, Wk, Wv, Wo);

    dim3 qkvgrid(BSROWS / 128, DD / 128, 3);    // (64, 8, 3)
    gemm_k<<<qkvgrid, 256, GEMM_SMEM>>>(bq, bk, bv, nullptr, -1);

    dim3 fgrid(SS / 64, BB * HH);               // (32, 64)
    flash_attn_kernel<<<fgrid, 128, FLASH_SMEM>>>(pm);

    dim3 ogrid(BSROWS / 128, DD / 128, 1);
    gemm_k<<<ogrid, 256, GEMM_SMEM>>>(bo, nullptr, nullptr, out, 3);
}